// round 9
// baseline (speedup 1.0000x reference)
#include <cuda_runtime.h>
#include <cuda_bf16.h>
#include <cstdint>

// Problem constants
#define Bb   8
#define Cc   768
#define Nn   256
#define Hh   12
#define Dd   64
#define HN   3072          // Hh*Nn
#define CNsz 196608        // Cc*Nn
#define SCALE 0.125f       // D^-0.5
#define GNT  24            // K tiles of 32 (K = 768)

// Scratch (allocation-free: __device__ globals)
__device__ float g_cp[Bb * CNsz];                 // proj(cross): [B, C, N] fp32
__device__ float g_Mpart[Bb * Hh * 2 * Dd * Dd];  // per-(b,h,nsplit) partial 64x64
__device__ __nv_bfloat16 g_Uhi[Bb * Nn * Cc];     // U hi plane [B, N, C]
__device__ __nv_bfloat16 g_Ulo[Bb * Nn * Cc];     // U lo plane [B, N, C]
__device__ __nv_bfloat16 g_Wph[Cc * Cc], g_Wpl[Cc * Cc];  // W_proj hi/lo
__device__ __nv_bfloat16 g_Wdh[Cc * Cc], g_Wdl[Cc * Cc];  // W_dep hi/lo
__device__ __nv_bfloat16 g_Xh[Bb * CNsz], g_Xl[Bb * CNsz]; // cross hi/lo

// ---- packed f32x2 helpers (for k_mpart) ----
#define FMA_F32X2(d, a, b, c) \
    asm("fma.rn.f32x2 %0, %1, %2, %3;" : "=l"(d) : "l"(a), "l"(b), "l"(c))

static __device__ __forceinline__ unsigned long long splat2(float x) {
    unsigned long long r;
    unsigned u = __float_as_uint(x);
    asm("mov.b64 %0, {%1, %1};" : "=l"(r) : "r"(u));
    return r;
}
static __device__ __forceinline__ float2 unpack2(unsigned long long v) {
    unsigned lo, hi;
    asm("mov.b64 {%0, %1}, %2;" : "=r"(lo), "=r"(hi) : "l"(v));
    return make_float2(__uint_as_float(lo), __uint_as_float(hi));
}

// ---- tensor-core primitives ----
static __device__ __forceinline__ uint32_t smem_u32(const void* p) {
    return (uint32_t)__cvta_generic_to_shared(p);
}

#define LDSM_X4(r0, r1, r2, r3, addr) \
    asm volatile("ldmatrix.sync.aligned.m8n8.x4.shared.b16 {%0,%1,%2,%3}, [%4];" \
        : "=r"(r0), "=r"(r1), "=r"(r2), "=r"(r3) : "r"(addr))

#define LDSM_X4_T(r0, r1, r2, r3, addr) \
    asm volatile("ldmatrix.sync.aligned.m8n8.x4.trans.shared.b16 {%0,%1,%2,%3}, [%4];" \
        : "=r"(r0), "=r"(r1), "=r"(r2), "=r"(r3) : "r"(addr))

#define MMA_BF16(D, a0, a1, a2, a3, b0, b1) \
    asm volatile("mma.sync.aligned.m16n8k16.row.col.f32.bf16.bf16.f32 " \
        "{%0,%1,%2,%3}, {%4,%5,%6,%7}, {%8,%9}, {%0,%1,%2,%3};" \
        : "+f"((D)[0]), "+f"((D)[1]), "+f"((D)[2]), "+f"((D)[3]) \
        : "r"(a0), "r"(a1), "r"(a2), "r"(a3), "r"(b0), "r"(b1))

// ---- cp.async ----
#define CP16(dst, src) \
    asm volatile("cp.async.cg.shared.global [%0], [%1], 16;" :: "r"(dst), "l"(src))
#define CP_COMMIT() asm volatile("cp.async.commit_group;")
#define CP_WAIT1()  asm volatile("cp.async.wait_group 1;")
#define CP_WAIT0()  asm volatile("cp.async.wait_group 0;")

// ============================================================================
// Kernel 0: split W_proj, W_dep, cross into bf16 hi/lo planes.
// One launch, 2688 blocks x 256 threads, 4 fp32/thread.
// ============================================================================
__global__ __launch_bounds__(256) void k_split_all(
    const float* __restrict__ wp, const float* __restrict__ wd,
    const float* __restrict__ x)
{
    const int i = blockIdx.x * 256 + threadIdx.x;   // 0 .. 688127
    const float* src;
    __nv_bfloat16 *hi, *lo;
    int off;
    if (i < 147456)        { src = wp; hi = g_Wph; lo = g_Wpl; off = i; }
    else if (i < 294912)   { src = wd; hi = g_Wdh; lo = g_Wdl; off = i - 147456; }
    else                   { src = x;  hi = g_Xh;  lo = g_Xl;  off = i - 294912; }

    float4 v = ((const float4*)src)[off];
    float f[4] = {v.x, v.y, v.z, v.w};
    uint32_t hw[2], lw[2];
#pragma unroll
    for (int j = 0; j < 2; j++) {
        __nv_bfloat16 h0 = __float2bfloat16(f[2 * j]);
        __nv_bfloat16 h1 = __float2bfloat16(f[2 * j + 1]);
        __nv_bfloat16 l0 = __float2bfloat16(f[2 * j] - __bfloat162float(h0));
        __nv_bfloat16 l1 = __float2bfloat16(f[2 * j + 1] - __bfloat162float(h1));
        __nv_bfloat162 hh(h0, h1), ll(l0, l1);
        hw[j] = *reinterpret_cast<uint32_t*>(&hh);
        lw[j] = *reinterpret_cast<uint32_t*>(&ll);
    }
    ((uint2*)hi)[off] = make_uint2(hw[0], hw[1]);
    ((uint2*)lo)[off] = make_uint2(lw[0], lw[1]);
}

// ============================================================================
// Kernel 1: cp = W_proj @ cross + b_proj. bf16 3-split, cp.async staging.
// Block 128(o) x 64(n), 4 warps (warp tile 32x64), BK=32 double-buffered.
// Grid (32, 6) = 192 blocks, 4 blocks/SM (48KB smem, <=128 regs).
// ============================================================================
__global__ __launch_bounds__(128, 4) void k_proj2(const float* __restrict__ bias)
{
    __shared__ uint4 As[2][128][8];   // [buf][o-row][chunk 0-3 hi / 4-7 lo], XOR swizzle
    __shared__ uint4 Bs[2][64][8];    // [buf][k 0-31 hi / 32-63 lo][n chunk]
    const int tid = threadIdx.x;
    const int wid = tid >> 5, lane = tid & 31;
    const int b = blockIdx.x >> 2;
    const int noff = (blockIdx.x & 3) * 64;
    const int otile = blockIdx.y * 128;

    const int wm = wid * 32;
    const int l7 = lane & 7, l15 = lane & 15, lsel = lane >> 4;
    const int g = lane >> 2, tc = lane & 3;

    // staging: A one row/thread; B: kr = tid>>2 (0..31), 2 chunks at (tid&3)*2
    const int arow = tid, am7 = arow & 7;
    const int bkr = tid >> 2, bns = (tid & 3) * 2, bk7 = bkr & 7;

    const __nv_bfloat16* Ahp = g_Wph + (size_t)(otile + arow) * Cc;
    const __nv_bfloat16* Alp = g_Wpl + (size_t)(otile + arow) * Cc;
    const __nv_bfloat16* Bhp = g_Xh + (size_t)b * CNsz + (size_t)bkr * Nn + noff + bns * 8;
    const __nv_bfloat16* Blp = g_Xl + (size_t)b * CNsz + (size_t)bkr * Nn + noff + bns * 8;

    float acc[2][8][4];
#pragma unroll
    for (int i = 0; i < 2; i++)
#pragma unroll
        for (int j = 0; j < 8; j++)
#pragma unroll
            for (int e = 0; e < 4; e++) acc[i][j][e] = 0.f;

    auto stage = [&](int buf, int k0) {
        const uint32_t ad = smem_u32(&As[buf][arow][0]);
#pragma unroll
        for (int c = 0; c < 4; c++) {
            CP16(ad + (uint32_t)((c ^ am7) * 16), (const char*)(Ahp + k0 + c * 8));
            CP16(ad + (uint32_t)(((c + 4) ^ am7) * 16), (const char*)(Alp + k0 + c * 8));
        }
        const uint32_t bdh = smem_u32(&Bs[buf][bkr][0]);
        const uint32_t bdl = smem_u32(&Bs[buf][bkr + 32][0]);
        const __nv_bfloat16* bh = Bhp + (size_t)k0 * Nn;
        const __nv_bfloat16* bl = Blp + (size_t)k0 * Nn;
#pragma unroll
        for (int i = 0; i < 2; i++) {
            CP16(bdh + (uint32_t)(((bns + i) ^ bk7) * 16), (const char*)(bh + i * 8));
            CP16(bdl + (uint32_t)(((bns + i) ^ bk7) * 16), (const char*)(bl + i * 8));
        }
    };

    stage(0, 0);
    CP_COMMIT();

    for (int kt = 0; kt < GNT; kt++) {
        const int cur = kt & 1;
        if (kt + 1 < GNT) {
            stage(cur ^ 1, (kt + 1) * 32);
            CP_COMMIT();
            CP_WAIT1();
        } else {
            CP_WAIT0();
        }
        __syncthreads();

        const uint32_t asb = smem_u32(&As[cur][0][0]);
        const uint32_t bsb = smem_u32(&Bs[cur][0][0]);
#pragma unroll
        for (int ks = 0; ks < 2; ks++) {
            uint32_t ah[2][4], al[2][4];
#pragma unroll
            for (int mf = 0; mf < 2; mf++) {
                const uint32_t rb = asb + (uint32_t)(wm + mf * 16 + l15) * 128;
                const int ch = (ks * 2 + lsel) ^ l7;
                const int cl = (ks * 2 + lsel + 4) ^ l7;
                LDSM_X4(ah[mf][0], ah[mf][1], ah[mf][2], ah[mf][3], rb + ch * 16);
                LDSM_X4(al[mf][0], al[mf][1], al[mf][2], al[mf][3], rb + cl * 16);
            }
#pragma unroll
            for (int np = 0; np < 4; np++) {
                const int p = (np * 2 + lsel) ^ l7;
                const uint32_t rb = bsb + (uint32_t)(ks * 16 + l15) * 128 + p * 16;
                uint32_t bh[4], bl[4];
                LDSM_X4_T(bh[0], bh[1], bh[2], bh[3], rb);
                LDSM_X4_T(bl[0], bl[1], bl[2], bl[3], rb + 32 * 128);
#pragma unroll
                for (int mf = 0; mf < 2; mf++) {
                    MMA_BF16(acc[mf][2 * np], ah[mf][0], ah[mf][1], ah[mf][2], ah[mf][3], bh[0], bh[1]);
                    MMA_BF16(acc[mf][2 * np], al[mf][0], al[mf][1], al[mf][2], al[mf][3], bh[0], bh[1]);
                    MMA_BF16(acc[mf][2 * np], ah[mf][0], ah[mf][1], ah[mf][2], ah[mf][3], bl[0], bl[1]);
                    MMA_BF16(acc[mf][2 * np + 1], ah[mf][0], ah[mf][1], ah[mf][2], ah[mf][3], bh[2], bh[3]);
                    MMA_BF16(acc[mf][2 * np + 1], al[mf][0], al[mf][1], al[mf][2], al[mf][3], bh[2], bh[3]);
                    MMA_BF16(acc[mf][2 * np + 1], ah[mf][0], ah[mf][1], ah[mf][2], ah[mf][3], bl[2], bl[3]);
                }
            }
        }
        __syncthreads();
    }

    // Epilogue: cp[o][n] + bias
#pragma unroll
    for (int mf = 0; mf < 2; mf++) {
        const int o = otile + wm + mf * 16 + g;
        const float b0v = bias[o], b1v = bias[o + 8];
        float* base = g_cp + (size_t)b * CNsz + (size_t)o * Nn + noff + tc * 2;
#pragma unroll
        for (int nf = 0; nf < 8; nf++) {
            *(float2*)(base + nf * 8) =
                make_float2(acc[mf][nf][0] + b0v, acc[mf][nf][1] + b0v);
            *(float2*)(base + nf * 8 + 8 * Nn) =
                make_float2(acc[mf][nf][2] + b1v, acc[mf][nf][3] + b1v);
        }
    }
}

// ============================================================================
// Kernel 2: Mpart[b,h,s][d,d'] = sum_{n in half s} cp[b,d*H+h,n]*cross[b,d'*H+h,n]
// Grid (12, 8, 2); f32x2 4x4 micro, K=128 per block.
// ============================================================================
__global__ __launch_bounds__(256) void k_mpart(const float* __restrict__ cross)
{
    __shared__ float As[16][64];
    __shared__ float Bs[16][64];
    const int h = blockIdx.x;
    const int b = blockIdx.y;
    const int s = blockIdx.z;
    const int tid = threadIdx.x;
    const int r = tid >> 4, c = tid & 15;
    const int lr = tid >> 2, lk = (tid & 3) * 4;

    const float* Ab = g_cp + (size_t)b * CNsz + h * Nn + s * 128;
    const float* Bp = cross + (size_t)b * CNsz + h * Nn + s * 128;

    unsigned long long acc[4][2];
#pragma unroll
    for (int i = 0; i < 4; i++) { acc[i][0] = 0ull; acc[i][1] = 0ull; }

    for (int k0 = 0; k0 < 128; k0 += 16) {
        float4 av = *(const float4*)(Ab + (size_t)lr * HN + k0 + lk);
        float4 bv = *(const float4*)(Bp + (size_t)lr * HN + k0 + lk);
        __syncthreads();
        As[lk + 0][lr] = av.x; As[lk + 1][lr] = av.y;
        As[lk + 2][lr] = av.z; As[lk + 3][lr] = av.w;
        Bs[lk + 0][lr] = bv.x; Bs[lk + 1][lr] = bv.y;
        Bs[lk + 2][lr] = bv.z; Bs[lk + 3][lr] = bv.w;
        __syncthreads();
#pragma unroll
        for (int k = 0; k < 16; k++) {
            float4 ar = *(const float4*)&As[k][r * 4];
            ulonglong2 bp = *(const ulonglong2*)&Bs[k][c * 4];
            unsigned long long sv;
            sv = splat2(ar.x);
            FMA_F32X2(acc[0][0], sv, bp.x, acc[0][0]);
            FMA_F32X2(acc[0][1], sv, bp.y, acc[0][1]);
            sv = splat2(ar.y);
            FMA_F32X2(acc[1][0], sv, bp.x, acc[1][0]);
            FMA_F32X2(acc[1][1], sv, bp.y, acc[1][1]);
            sv = splat2(ar.z);
            FMA_F32X2(acc[2][0], sv, bp.x, acc[2][0]);
            FMA_F32X2(acc[2][1], sv, bp.y, acc[2][1]);
            sv = splat2(ar.w);
            FMA_F32X2(acc[3][0], sv, bp.x, acc[3][0]);
            FMA_F32X2(acc[3][1], sv, bp.y, acc[3][1]);
        }
    }

    float* mp = g_Mpart + (((size_t)b * Hh + h) * 2 + s) * 4096;
#pragma unroll
    for (int i = 0; i < 4; i++) {
        float2 lo = unpack2(acc[i][0]);
        float2 hi = unpack2(acc[i][1]);
        *(float4*)(mp + (size_t)(r * 4 + i) * 64 + c * 4) =
            make_float4(lo.x, lo.y, hi.x, hi.y);
    }
}

// ============================================================================
// Kernel 3: U rows = scale * x-row(m) . M[b]; fused (h,s)-reduction of Mpart.
// Grid (96, 4); emits bf16 hi/lo planes for the deproj tensor-core GEMM.
// ============================================================================
__global__ __launch_bounds__(256) void k_out(const float* __restrict__ x_ori)
{
    __shared__ float Ms[64][16];
    const int b = blockIdx.x / Hh;
    const int hp = blockIdx.x % Hh;
    const int q = blockIdx.y;        // d' quarter
    const int tid = threadIdx.x;

    for (int idx = tid; idx < 1024; idx += 256) {
        const int d = idx >> 4, c = idx & 15;
        const float* mp = g_Mpart + ((size_t)b * Hh * 2) * 4096 + d * 64 + q * 16 + c;
        float sacc = 0.f;
#pragma unroll
        for (int hs = 0; hs < Hh * 2; hs++) sacc += mp[(size_t)hs * 4096];
        Ms[d][c] = sacc;
    }
    __syncthreads();

    const float* xb = x_ori + (size_t)b * CNsz + hp * Nn + tid;

    float4 acc[4];
#pragma unroll
    for (int e = 0; e < 4; e++) acc[e] = make_float4(0.f, 0.f, 0.f, 0.f);

    for (int d0 = 0; d0 < 64; d0 += 8) {
        float xr[8];
#pragma unroll
        for (int i = 0; i < 8; i++) xr[i] = xb[(size_t)(d0 + i) * HN];
#pragma unroll
        for (int i = 0; i < 8; i++) {
            const float4* Mr = (const float4*)&Ms[d0 + i][0];
            const float xv = xr[i];
#pragma unroll
            for (int e = 0; e < 4; e++) {
                float4 mv = Mr[e];
                acc[e].x += xv * mv.x;
                acc[e].y += xv * mv.y;
                acc[e].z += xv * mv.z;
                acc[e].w += xv * mv.w;
            }
        }
    }

    const int m = hp * Nn + tid;
    const int nf = m / Hh;
    const int hf = m - nf * Hh;
    const size_t off = ((size_t)b * Nn + nf) * Cc + hf * Dd + q * 16;

    float v[16];
    *(float4*)&v[0] = acc[0]; *(float4*)&v[4] = acc[1];
    *(float4*)&v[8] = acc[2]; *(float4*)&v[12] = acc[3];
    uint32_t hw[8], lw[8];
#pragma unroll
    for (int i = 0; i < 8; i++) {
        float f0 = v[2 * i] * SCALE, f1 = v[2 * i + 1] * SCALE;
        __nv_bfloat16 h0 = __float2bfloat16(f0);
        __nv_bfloat16 h1 = __float2bfloat16(f1);
        __nv_bfloat16 l0 = __float2bfloat16(f0 - __bfloat162float(h0));
        __nv_bfloat16 l1 = __float2bfloat16(f1 - __bfloat162float(h1));
        __nv_bfloat162 hh(h0, h1), ll(l0, l1);
        hw[i] = *reinterpret_cast<uint32_t*>(&hh);
        lw[i] = *reinterpret_cast<uint32_t*>(&ll);
    }
    *(uint4*)(g_Uhi + off)     = make_uint4(hw[0], hw[1], hw[2], hw[3]);
    *(uint4*)(g_Uhi + off + 8) = make_uint4(hw[4], hw[5], hw[6], hw[7]);
    *(uint4*)(g_Ulo + off)     = make_uint4(lw[0], lw[1], lw[2], lw[3]);
    *(uint4*)(g_Ulo + off + 8) = make_uint4(lw[4], lw[5], lw[6], lw[7]);
}

// ============================================================================
// Kernel 4: out = x_ori + b_dep + U @ W_dep^T. bf16 3-split, cp.async staging.
// Block 128(o) x 64(n), 4 warps (32x64), double-buffered. Grid (32, 6).
// ============================================================================
__global__ __launch_bounds__(128, 4) void k_deproj2(
    const float* __restrict__ bdep, const float* __restrict__ x_ori,
    float* __restrict__ out)
{
    __shared__ uint4 As[2][128][8];   // [buf][o][chunk hi 0-3 / lo 4-7]
    __shared__ uint4 Bs[2][64][8];    // [buf][n][chunk hi 0-3 / lo 4-7]
    const int tid = threadIdx.x;
    const int wid = tid >> 5, lane = tid & 31;
    const int b = blockIdx.x >> 2;
    const int noff = (blockIdx.x & 3) * 64;
    const int otile = blockIdx.y * 128;

    const int wm = wid * 32;
    const int l7 = lane & 7, l15 = lane & 15, lsel = lane >> 4;
    const int ksel = (lane >> 3) & 1;
    const int rowNl = (lane & 7) + (lsel << 3);
    const int g = lane >> 2, tc = lane & 3;

    const int arow = tid, am7 = arow & 7;
    const int brow = tid >> 1, bkh = (tid & 1) * 2, bn7 = brow & 7;

    const __nv_bfloat16* Ahp = g_Wdh + (size_t)(otile + arow) * Cc;
    const __nv_bfloat16* Alp = g_Wdl + (size_t)(otile + arow) * Cc;
    const __nv_bfloat16* Uhp = g_Uhi + ((size_t)b * Nn + noff + brow) * Cc + (tid & 1) * 16;
    const __nv_bfloat16* Ulp = g_Ulo + ((size_t)b * Nn + noff + brow) * Cc + (tid & 1) * 16;

    float acc[2][8][4];
#pragma unroll
    for (int i = 0; i < 2; i++)
#pragma unroll
        for (int j = 0; j < 8; j++)
#pragma unroll
            for (int e = 0; e < 4; e++) acc[i][j][e] = 0.f;

    auto stage = [&](int buf, int k0) {
        const uint32_t ad = smem_u32(&As[buf][arow][0]);
#pragma unroll
        for (int c = 0; c < 4; c++) {
            CP16(ad + (uint32_t)((c ^ am7) * 16), (const char*)(Ahp + k0 + c * 8));
            CP16(ad + (uint32_t)(((c + 4) ^ am7) * 16), (const char*)(Alp + k0 + c * 8));
        }
        const uint32_t bd = smem_u32(&Bs[buf][brow][0]);
#pragma unroll
        for (int i = 0; i < 2; i++) {
            CP16(bd + (uint32_t)(((bkh + i) ^ bn7) * 16), (const char*)(Uhp + k0 + i * 8));
            CP16(bd + (uint32_t)(((bkh + i + 4) ^ bn7) * 16), (const char*)(Ulp + k0 + i * 8));
        }
    };

    stage(0, 0);
    CP_COMMIT();

    for (int kt = 0; kt < GNT; kt++) {
        const int cur = kt & 1;
        if (kt + 1 < GNT) {
            stage(cur ^ 1, (kt + 1) * 32);
            CP_COMMIT();
            CP_WAIT1();
        } else {
            CP_WAIT0();
        }
        __syncthreads();

        const uint32_t asb = smem_u32(&As[cur][0][0]);
        const uint32_t bsb = smem_u32(&Bs[cur][0][0]);
#pragma unroll
        for (int ks = 0; ks < 2; ks++) {
            uint32_t ah[2][4], al[2][4];
#pragma unroll
            for (int mf = 0; mf < 2; mf++) {
                const uint32_t rb = asb + (uint32_t)(wm + mf * 16 + l15) * 128;
                const int ch = (ks * 2 + lsel) ^ l7;
                const int cl = (ks * 2 + lsel + 4) ^ l7;
                LDSM_X4(ah[mf][0], ah[mf][1], ah[mf][2], ah[mf][3], rb + ch * 16);
                LDSM_X4(al[mf][0], al[mf][1], al[mf][2], al[mf][3], rb + cl * 16);
            }
#pragma unroll
            for (int np = 0; np < 4; np++) {
                const int rowN = np * 16 + rowNl;
                const int ch = (ks * 2 + ksel) ^ l7;
                const int cl = (ks * 2 + ksel + 4) ^ l7;
                const uint32_t rb = bsb + (uint32_t)rowN * 128;
                uint32_t bh[4], bl[4];
                LDSM_X4(bh[0], bh[1], bh[2], bh[3], rb + ch * 16);
                LDSM_X4(bl[0], bl[1], bl[2], bl[3], rb + cl * 16);
#pragma unroll
                for (int mf = 0; mf < 2; mf++) {
                    MMA_BF16(acc[mf][2 * np], ah[mf][0], ah[mf][1], ah[mf][2], ah[mf][3], bh[0], bh[1]);
                    MMA_BF16(acc[mf][2 * np], al[mf][0], al[mf][1], al[mf][2], al[mf][3], bh[0], bh[1]);
                    MMA_BF16(acc[mf][2 * np], ah[mf][0], ah[mf][1], ah[mf][2], ah[mf][3], bl[0], bl[1]);
                    MMA_BF16(acc[mf][2 * np + 1], ah[mf][0], ah[mf][1], ah[mf][2], ah[mf][3], bh[2], bh[3]);
                    MMA_BF16(acc[mf][2 * np + 1], al[mf][0], al[mf][1], al[mf][2], al[mf][3], bh[2], bh[3]);
                    MMA_BF16(acc[mf][2 * np + 1], ah[mf][0], ah[mf][1], ah[mf][2], ah[mf][3], bl[2], bl[3]);
                }
            }
        }
        __syncthreads();
    }

    // Epilogue: + bias + skip
#pragma unroll
    for (int mf = 0; mf < 2; mf++) {
        const int o = otile + wm + mf * 16 + g;
        const float b0v = bdep[o], b1v = bdep[o + 8];
        const size_t base = (size_t)b * CNsz + (size_t)o * Nn + noff + tc * 2;
#pragma unroll
        for (int nf = 0; nf < 8; nf++) {
            const size_t i0 = base + nf * 8;
            float2 x0 = *(const float2*)(x_ori + i0);
            float2 x1 = *(const float2*)(x_ori + i0 + 8 * Nn);
            *(float2*)(out + i0) =
                make_float2(acc[mf][nf][0] + b0v + x0.x, acc[mf][nf][1] + b0v + x0.y);
            *(float2*)(out + i0 + 8 * Nn) =
                make_float2(acc[mf][nf][2] + b1v + x1.x, acc[mf][nf][3] + b1v + x1.y);
        }
    }
}

// ============================================================================
// Launch
// ============================================================================
extern "C" void kernel_launch(void* const* d_in, const int* in_sizes, int n_in,
                              void* d_out, int out_size)
{
    (void)in_sizes; (void)n_in; (void)out_size;
    const float* x_ori  = (const float*)d_in[0];
    const float* cross  = (const float*)d_in[1];
    const float* W_proj = (const float*)d_in[2];
    const float* b_proj = (const float*)d_in[3];
    const float* W_dep  = (const float*)d_in[4];
    const float* b_dep  = (const float*)d_in[5];
    float* out = (float*)d_out;

    k_split_all<<<2688, 256>>>(W_proj, W_dep, cross);
    k_proj2<<<dim3(32, 6), 128>>>(b_proj);
    k_mpart<<<dim3(Hh, Bb, 2), 256>>>(cross);
    k_out<<<dim3(Bb * Hh, 4), 256>>>(x_ori);
    k_deproj2<<<dim3(32, 6), 128>>>(b_dep, x_ori, out);
}

// round 11
// speedup vs baseline: 1.2704x; 1.2704x over previous
#include <cuda_runtime.h>
#include <cuda_bf16.h>
#include <cstdint>

// Problem constants
#define Bb   8
#define Cc   768
#define Nn   256
#define Hh   12
#define Dd   64
#define HN   3072          // Hh*Nn
#define CNsz 196608        // Cc*Nn
#define SCALE 0.125f       // D^-0.5
#define GNT  24            // K tiles of 32 (K = 768)

// Scratch (allocation-free: __device__ globals)
__device__ __align__(16) float g_cp[Bb * CNsz];                // proj out [B,C,N]
__device__ __align__(16) float g_Mpart[Bb * Hh * Dd * Dd];     // per-(b,h) 64x64
__device__ __align__(16) __nv_bfloat16 g_Uhi[Bb * Nn * Cc];    // U hi [B,N,C]
__device__ __align__(16) __nv_bfloat16 g_Ulo[Bb * Nn * Cc];    // U lo [B,N,C]
__device__ __align__(16) __nv_bfloat16 g_Wph[Cc * Cc], g_Wpl[Cc * Cc];
__device__ __align__(16) __nv_bfloat16 g_Wdh[Cc * Cc], g_Wdl[Cc * Cc];
__device__ __align__(16) __nv_bfloat16 g_Xh[Bb * CNsz], g_Xl[Bb * CNsz]; // cross planes [b][c][n]

// ---- packed f32x2 helpers (for k_mpart) ----
#define FMA_F32X2(d, a, b, c) \
    asm("fma.rn.f32x2 %0, %1, %2, %3;" : "=l"(d) : "l"(a), "l"(b), "l"(c))

static __device__ __forceinline__ unsigned long long splat2(float x) {
    unsigned long long r;
    unsigned u = __float_as_uint(x);
    asm("mov.b64 %0, {%1, %1};" : "=l"(r) : "r"(u));
    return r;
}
static __device__ __forceinline__ float2 unpack2(unsigned long long v) {
    unsigned lo, hi;
    asm("mov.b64 {%0, %1}, %2;" : "=r"(lo), "=r"(hi) : "l"(v));
    return make_float2(__uint_as_float(lo), __uint_as_float(hi));
}

// ---- tensor-core primitives ----
static __device__ __forceinline__ uint32_t smem_u32(const void* p) {
    return (uint32_t)__cvta_generic_to_shared(p);
}

#define LDSM_X4(r0, r1, r2, r3, addr) \
    asm volatile("ldmatrix.sync.aligned.m8n8.x4.shared.b16 {%0,%1,%2,%3}, [%4];" \
        : "=r"(r0), "=r"(r1), "=r"(r2), "=r"(r3) : "r"(addr))

#define LDSM_X4_T(r0, r1, r2, r3, addr) \
    asm volatile("ldmatrix.sync.aligned.m8n8.x4.trans.shared.b16 {%0,%1,%2,%3}, [%4];" \
        : "=r"(r0), "=r"(r1), "=r"(r2), "=r"(r3) : "r"(addr))

#define MMA_BF16(D, a0, a1, a2, a3, b0, b1) \
    asm volatile("mma.sync.aligned.m16n8k16.row.col.f32.bf16.bf16.f32 " \
        "{%0,%1,%2,%3}, {%4,%5,%6,%7}, {%8,%9}, {%0,%1,%2,%3};" \
        : "+f"((D)[0]), "+f"((D)[1]), "+f"((D)[2]), "+f"((D)[3]) \
        : "r"(a0), "r"(a1), "r"(a2), "r"(a3), "r"(b0), "r"(b1))

// ============================================================================
// Kernel 0: split W_proj / W_dep / cross into bf16 hi/lo planes (layouts kept).
// 2688 blocks x 256 threads, one float4 per thread.
// ============================================================================
__global__ __launch_bounds__(256) void k_split_all(
    const float* __restrict__ wp, const float* __restrict__ wd,
    const float* __restrict__ x)
{
    const int i = blockIdx.x * 256 + threadIdx.x;   // 0 .. 688127
    const float* src;
    __nv_bfloat16 *hi, *lo;
    int off;
    if (i < 147456)      { src = wp; hi = g_Wph; lo = g_Wpl; off = i; }
    else if (i < 294912) { src = wd; hi = g_Wdh; lo = g_Wdl; off = i - 147456; }
    else                 { src = x;  hi = g_Xh;  lo = g_Xl;  off = i - 294912; }

    float4 v = ((const float4*)src)[off];
    float f[4] = {v.x, v.y, v.z, v.w};
    uint32_t hw[2], lw[2];
#pragma unroll
    for (int j = 0; j < 2; j++) {
        __nv_bfloat16 h0 = __float2bfloat16(f[2 * j]);
        __nv_bfloat16 h1 = __float2bfloat16(f[2 * j + 1]);
        __nv_bfloat16 l0 = __float2bfloat16(f[2 * j] - __bfloat162float(h0));
        __nv_bfloat16 l1 = __float2bfloat16(f[2 * j + 1] - __bfloat162float(h1));
        __nv_bfloat162 hh(h0, h1), ll(l0, l1);
        hw[j] = *reinterpret_cast<uint32_t*>(&hh);
        lw[j] = *reinterpret_cast<uint32_t*>(&ll);
    }
    ((uint2*)hi)[off] = make_uint2(hw[0], hw[1]);
    ((uint2*)lo)[off] = make_uint2(lw[0], lw[1]);
}

// ============================================================================
// Kernel 1: cp = W_proj @ cross + b_proj. bf16 3-split tensor core.
// Block 128(o) x 64(n), 8 warps of 32x32, BK=32 double-buffered. Grid (32,6).
// Identical control flow to the 101.1us winner; staging now reads pre-split
// planes (uint4 in, uint4 out — no conversion math in the hot loop).
// ============================================================================
__global__ __launch_bounds__(256, 2) void k_proj_mma(const float* __restrict__ bias)
{
    __shared__ uint4 As4[2][128][8];   // [buf][m][chunk 0-3 hi / 4-7 lo], XOR swizzle
    __shared__ uint4 Bs4[2][64][8];    // [buf][k 0-31 hi / 32-63 lo][n chunk]
    const int tid = threadIdx.x;
    const int wid = tid >> 5, lane = tid & 31;
    const int b = blockIdx.x >> 2;
    const int noff = (blockIdx.x & 3) * 64;
    const int otile = blockIdx.y * 128;

    const int wm = (wid >> 1) * 32;   // 0,32,64,96
    const int wn = (wid & 1) * 32;    // 0,32
    const int l7 = lane & 7, l15 = lane & 15, lsel = lane >> 4;
    const int g = lane >> 2, tc = lane & 3;

    // staging indices (same geometry as winner)
    const int arow = tid >> 2, akseg = tid & 3;    // A rows arow, arow+64
    const int am7 = arow & 7;
    const int bkrow = tid >> 3, bnseg = tid & 7;   // B k-row, n chunk
    const int bk7 = bkrow & 7;

    const __nv_bfloat16* Ahp = g_Wph + (size_t)(otile + arow) * Cc + akseg * 8;
    const __nv_bfloat16* Alp = g_Wpl + (size_t)(otile + arow) * Cc + akseg * 8;
    const __nv_bfloat16* Bhp = g_Xh + (size_t)b * CNsz + (size_t)bkrow * Nn + noff + bnseg * 8;
    const __nv_bfloat16* Blp = g_Xl + (size_t)b * CNsz + (size_t)bkrow * Nn + noff + bnseg * 8;

    const uint32_t as_base = smem_u32(&As4[0][0][0]);
    const uint32_t bs_base = smem_u32(&Bs4[0][0][0]);

    float acc[2][4][4];
#pragma unroll
    for (int i = 0; i < 2; i++)
#pragma unroll
        for (int j = 0; j < 4; j++)
#pragma unroll
            for (int e = 0; e < 4; e++) acc[i][j][e] = 0.f;

    uint4 pah0, pal0, pah1, pal1, pbh, pbl;
    pah0 = *(const uint4*)(Ahp);
    pal0 = *(const uint4*)(Alp);
    pah1 = *(const uint4*)(Ahp + (size_t)64 * Cc);
    pal1 = *(const uint4*)(Alp + (size_t)64 * Cc);
    pbh  = *(const uint4*)(Bhp);
    pbl  = *(const uint4*)(Blp);

    {
        As4[0][arow][akseg ^ am7] = pah0;
        As4[0][arow][(akseg + 4) ^ am7] = pal0;
        As4[0][arow + 64][akseg ^ am7] = pah1;
        As4[0][arow + 64][(akseg + 4) ^ am7] = pal1;
        Bs4[0][bkrow][bnseg ^ bk7] = pbh;
        Bs4[0][bkrow + 32][bnseg ^ bk7] = pbl;
    }
    __syncthreads();

    for (int kt = 0; kt < GNT; kt++) {
        const int cur = kt & 1;
        if (kt + 1 < GNT) {
            Ahp += 32; Alp += 32;
            Bhp += (size_t)32 * Nn; Blp += (size_t)32 * Nn;
            pah0 = *(const uint4*)(Ahp);
            pal0 = *(const uint4*)(Alp);
            pah1 = *(const uint4*)(Ahp + (size_t)64 * Cc);
            pal1 = *(const uint4*)(Alp + (size_t)64 * Cc);
            pbh  = *(const uint4*)(Bhp);
            pbl  = *(const uint4*)(Blp);
        }

        const uint32_t asb = as_base + (uint32_t)cur * 16384;
        const uint32_t bsb = bs_base + (uint32_t)cur * 8192;
#pragma unroll
        for (int ks = 0; ks < 2; ks++) {
            const int k0 = ks * 16;
            uint32_t ah[2][4], al[2][4];
#pragma unroll
            for (int mf = 0; mf < 2; mf++) {
                const uint32_t rbase = asb + (uint32_t)(wm + mf * 16 + l15) * 128;
                const int ch = ((k0 >> 3) + lsel) ^ l7;
                const int cl = ((k0 >> 3) + lsel + 4) ^ l7;
                LDSM_X4(ah[mf][0], ah[mf][1], ah[mf][2], ah[mf][3], rbase + ch * 16);
                LDSM_X4(al[mf][0], al[mf][1], al[mf][2], al[mf][3], rbase + cl * 16);
            }
#pragma unroll
            for (int np = 0; np < 2; np++) {
                const int c = (wn >> 3) + np * 2 + lsel;
                const int p = c ^ l7;
                const uint32_t rb = bsb + (uint32_t)(k0 + l15) * 128 + p * 16;
                uint32_t bh[4], bl[4];
                LDSM_X4_T(bh[0], bh[1], bh[2], bh[3], rb);
                LDSM_X4_T(bl[0], bl[1], bl[2], bl[3], rb + 32 * 128);
#pragma unroll
                for (int mf = 0; mf < 2; mf++) {
                    MMA_BF16(acc[mf][2 * np], ah[mf][0], ah[mf][1], ah[mf][2], ah[mf][3], bh[0], bh[1]);
                    MMA_BF16(acc[mf][2 * np], al[mf][0], al[mf][1], al[mf][2], al[mf][3], bh[0], bh[1]);
                    MMA_BF16(acc[mf][2 * np], ah[mf][0], ah[mf][1], ah[mf][2], ah[mf][3], bl[0], bl[1]);
                    MMA_BF16(acc[mf][2 * np + 1], ah[mf][0], ah[mf][1], ah[mf][2], ah[mf][3], bh[2], bh[3]);
                    MMA_BF16(acc[mf][2 * np + 1], al[mf][0], al[mf][1], al[mf][2], al[mf][3], bh[2], bh[3]);
                    MMA_BF16(acc[mf][2 * np + 1], ah[mf][0], ah[mf][1], ah[mf][2], ah[mf][3], bl[2], bl[3]);
                }
            }
        }

        if (kt + 1 < GNT) {
            const int nxt = cur ^ 1;
            __syncthreads();
            As4[nxt][arow][akseg ^ am7] = pah0;
            As4[nxt][arow][(akseg + 4) ^ am7] = pal0;
            As4[nxt][arow + 64][akseg ^ am7] = pah1;
            As4[nxt][arow + 64][(akseg + 4) ^ am7] = pal1;
            Bs4[nxt][bkrow][bnseg ^ bk7] = pbh;
            Bs4[nxt][bkrow + 32][bnseg ^ bk7] = pbl;
            __syncthreads();
        }
    }

    // Epilogue: cp[o][n] + bias
#pragma unroll
    for (int mf = 0; mf < 2; mf++) {
        const int o = otile + wm + mf * 16 + g;
        const float b0v = bias[o], b1v = bias[o + 8];
        float* base = g_cp + (size_t)b * CNsz + (size_t)o * Nn + noff + wn + tc * 2;
#pragma unroll
        for (int nf = 0; nf < 4; nf++) {
            *(float2*)(base + nf * 8) =
                make_float2(acc[mf][nf][0] + b0v, acc[mf][nf][1] + b0v);
            *(float2*)(base + nf * 8 + 8 * Nn) =
                make_float2(acc[mf][nf][2] + b1v, acc[mf][nf][3] + b1v);
        }
    }
}

// ============================================================================
// Kernel 2: Mpart[b,h][d,d'] = sum_n cp[b,d*H+h,n] * cross[b,d'*H+h,n]
// One block per (b,h); f32x2 4x4 micro. (Unchanged from the 101.1 winner.)
// ============================================================================
__global__ __launch_bounds__(256) void k_mpart(const float* __restrict__ cross)
{
    __shared__ float As[16][64];
    __shared__ float Bs[16][64];
    const int h = blockIdx.x;
    const int b = blockIdx.y;
    const int tid = threadIdx.x;
    const int r = tid >> 4, c = tid & 15;
    const int lr = tid >> 2, lk = (tid & 3) * 4;

    const float* Ab = g_cp + (size_t)b * CNsz + h * Nn;
    const float* Bp = cross + (size_t)b * CNsz + h * Nn;

    unsigned long long acc[4][2];
#pragma unroll
    for (int i = 0; i < 4; i++) { acc[i][0] = 0ull; acc[i][1] = 0ull; }

    for (int k0 = 0; k0 < Nn; k0 += 16) {
        float4 av = *(const float4*)(Ab + (size_t)lr * HN + k0 + lk);
        float4 bv = *(const float4*)(Bp + (size_t)lr * HN + k0 + lk);
        __syncthreads();
        As[lk + 0][lr] = av.x; As[lk + 1][lr] = av.y;
        As[lk + 2][lr] = av.z; As[lk + 3][lr] = av.w;
        Bs[lk + 0][lr] = bv.x; Bs[lk + 1][lr] = bv.y;
        Bs[lk + 2][lr] = bv.z; Bs[lk + 3][lr] = bv.w;
        __syncthreads();
#pragma unroll
        for (int k = 0; k < 16; k++) {
            float4 ar = *(const float4*)&As[k][r * 4];
            ulonglong2 bp = *(const ulonglong2*)&Bs[k][c * 4];
            unsigned long long sv;
            sv = splat2(ar.x);
            FMA_F32X2(acc[0][0], sv, bp.x, acc[0][0]);
            FMA_F32X2(acc[0][1], sv, bp.y, acc[0][1]);
            sv = splat2(ar.y);
            FMA_F32X2(acc[1][0], sv, bp.x, acc[1][0]);
            FMA_F32X2(acc[1][1], sv, bp.y, acc[1][1]);
            sv = splat2(ar.z);
            FMA_F32X2(acc[2][0], sv, bp.x, acc[2][0]);
            FMA_F32X2(acc[2][1], sv, bp.y, acc[2][1]);
            sv = splat2(ar.w);
            FMA_F32X2(acc[3][0], sv, bp.x, acc[3][0]);
            FMA_F32X2(acc[3][1], sv, bp.y, acc[3][1]);
        }
    }

    float* mp = g_Mpart + ((size_t)b * Hh + h) * 4096;
#pragma unroll
    for (int i = 0; i < 4; i++) {
        float2 lo = unpack2(acc[i][0]);
        float2 hi = unpack2(acc[i][1]);
        *(float4*)(mp + (size_t)(r * 4 + i) * 64 + c * 4) =
            make_float4(lo.x, lo.y, hi.x, hi.y);
    }
}

// ============================================================================
// Kernel 3: U rows = scale * x-row(m) . M[b]; fused h-reduction of Mpart.
// Grid (96, 4); emits bf16 hi/lo planes. (Unchanged from the 101.1 winner.)
// ============================================================================
__global__ __launch_bounds__(256) void k_out(const float* __restrict__ x_ori)
{
    __shared__ float Ms[64][16];
    const int b = blockIdx.x / Hh;
    const int hp = blockIdx.x % Hh;
    const int q = blockIdx.y;        // d' quarter
    const int tid = threadIdx.x;

    for (int idx = tid; idx < 1024; idx += 256) {
        const int d = idx >> 4, c = idx & 15;
        const float* mp = g_Mpart + ((size_t)b * Hh) * 4096 + d * 64 + q * 16 + c;
        float sacc = 0.f;
#pragma unroll
        for (int h = 0; h < Hh; h++) sacc += mp[(size_t)h * 4096];
        Ms[d][c] = sacc;
    }
    __syncthreads();

    const float* xb = x_ori + (size_t)b * CNsz + hp * Nn + tid;

    float4 acc[4];
#pragma unroll
    for (int e = 0; e < 4; e++) acc[e] = make_float4(0.f, 0.f, 0.f, 0.f);

    for (int d0 = 0; d0 < 64; d0 += 8) {
        float xr[8];
#pragma unroll
        for (int i = 0; i < 8; i++) xr[i] = xb[(size_t)(d0 + i) * HN];
#pragma unroll
        for (int i = 0; i < 8; i++) {
            const float4* Mr = (const float4*)&Ms[d0 + i][0];
            const float xv = xr[i];
#pragma unroll
            for (int e = 0; e < 4; e++) {
                float4 mv = Mr[e];
                acc[e].x += xv * mv.x;
                acc[e].y += xv * mv.y;
                acc[e].z += xv * mv.z;
                acc[e].w += xv * mv.w;
            }
        }
    }

    const int m = hp * Nn + tid;
    const int nf = m / Hh;
    const int hf = m - nf * Hh;
    const size_t off = ((size_t)b * Nn + nf) * Cc + hf * Dd + q * 16;

    float v[16];
    *(float4*)&v[0] = acc[0]; *(float4*)&v[4] = acc[1];
    *(float4*)&v[8] = acc[2]; *(float4*)&v[12] = acc[3];
    uint32_t hw[8], lw[8];
#pragma unroll
    for (int i = 0; i < 8; i++) {
        float f0 = v[2 * i] * SCALE, f1 = v[2 * i + 1] * SCALE;
        __nv_bfloat16 h0 = __float2bfloat16(f0);
        __nv_bfloat16 h1 = __float2bfloat16(f1);
        __nv_bfloat16 l0 = __float2bfloat16(f0 - __bfloat162float(h0));
        __nv_bfloat16 l1 = __float2bfloat16(f1 - __bfloat162float(h1));
        __nv_bfloat162 hh(h0, h1), ll(l0, l1);
        hw[i] = *reinterpret_cast<uint32_t*>(&hh);
        lw[i] = *reinterpret_cast<uint32_t*>(&ll);
    }
    *(uint4*)(g_Uhi + off)     = make_uint4(hw[0], hw[1], hw[2], hw[3]);
    *(uint4*)(g_Uhi + off + 8) = make_uint4(hw[4], hw[5], hw[6], hw[7]);
    *(uint4*)(g_Ulo + off)     = make_uint4(lw[0], lw[1], lw[2], lw[3]);
    *(uint4*)(g_Ulo + off + 8) = make_uint4(lw[4], lw[5], lw[6], lw[7]);
}

// ============================================================================
// Kernel 4: out = x_ori + b_dep + U @ W_dep^T. bf16 3-split tensor core.
// Same 128x64 winner skeleton; A from pre-split W_dep planes, B from U planes.
// ============================================================================
__global__ __launch_bounds__(256, 2) void k_deproj_mma(
    const float* __restrict__ bdep, const float* __restrict__ x_ori,
    float* __restrict__ out)
{
    __shared__ uint4 As4[2][128][8];   // [buf][o][chunk hi 0-3 / lo 4-7]
    __shared__ uint4 Bs4[2][64][8];    // [buf][n][chunk hi 0-3 / lo 4-7]
    const int tid = threadIdx.x;
    const int wid = tid >> 5, lane = tid & 31;
    const int b = blockIdx.x >> 2;
    const int noff = (blockIdx.x & 3) * 64;
    const int otile = blockIdx.y * 128;

    const int wm = (wid >> 1) * 32;
    const int wn = (wid & 1) * 32;
    const int l7 = lane & 7, l15 = lane & 15, lsel = lane >> 4;
    const int ksel = (lane >> 3) & 1;
    const int rowNl = (lane & 7) + (lsel << 3);
    const int g = lane >> 2, tc = lane & 3;

    const int arow = tid >> 2, akseg = tid & 3;
    const int am7 = arow & 7;
    const int bnrow = tid >> 3, bc = tid & 7;      // B: n-rows bnrow, bnrow+32
    const int bn7 = bnrow & 7;

    const __nv_bfloat16* Ahp = g_Wdh + (size_t)(otile + arow) * Cc + akseg * 8;
    const __nv_bfloat16* Alp = g_Wdl + (size_t)(otile + arow) * Cc + akseg * 8;
    const __nv_bfloat16* Usrc = (bc < 4) ? g_Uhi : g_Ulo;
    const __nv_bfloat16* Ugp =
        Usrc + ((size_t)b * Nn + noff + bnrow) * Cc + (bc & 3) * 8;

    const uint32_t as_base = smem_u32(&As4[0][0][0]);
    const uint32_t bs_base = smem_u32(&Bs4[0][0][0]);

    float acc[2][4][4];
#pragma unroll
    for (int i = 0; i < 2; i++)
#pragma unroll
        for (int j = 0; j < 4; j++)
#pragma unroll
            for (int e = 0; e < 4; e++) acc[i][j][e] = 0.f;

    uint4 pah0, pal0, pah1, pal1, u0, u1;
    pah0 = *(const uint4*)(Ahp);
    pal0 = *(const uint4*)(Alp);
    pah1 = *(const uint4*)(Ahp + (size_t)64 * Cc);
    pal1 = *(const uint4*)(Alp + (size_t)64 * Cc);
    u0 = *(const uint4*)(Ugp);
    u1 = *(const uint4*)(Ugp + (size_t)32 * Cc);

    {
        As4[0][arow][akseg ^ am7] = pah0;
        As4[0][arow][(akseg + 4) ^ am7] = pal0;
        As4[0][arow + 64][akseg ^ am7] = pah1;
        As4[0][arow + 64][(akseg + 4) ^ am7] = pal1;
        Bs4[0][bnrow][bc ^ bn7] = u0;
        Bs4[0][bnrow + 32][bc ^ bn7] = u1;
    }
    __syncthreads();

    for (int kt = 0; kt < GNT; kt++) {
        const int cur = kt & 1;
        if (kt + 1 < GNT) {
            Ahp += 32; Alp += 32; Ugp += 32;
            pah0 = *(const uint4*)(Ahp);
            pal0 = *(const uint4*)(Alp);
            pah1 = *(const uint4*)(Ahp + (size_t)64 * Cc);
            pal1 = *(const uint4*)(Alp + (size_t)64 * Cc);
            u0 = *(const uint4*)(Ugp);
            u1 = *(const uint4*)(Ugp + (size_t)32 * Cc);
        }

        const uint32_t asb = as_base + (uint32_t)cur * 16384;
        const uint32_t bsb = bs_base + (uint32_t)cur * 8192;
#pragma unroll
        for (int ks = 0; ks < 2; ks++) {
            const int k0 = ks * 16;
            uint32_t ah[2][4], al[2][4];
#pragma unroll
            for (int mf = 0; mf < 2; mf++) {
                const uint32_t rbase = asb + (uint32_t)(wm + mf * 16 + l15) * 128;
                const int ch = ((k0 >> 3) + lsel) ^ l7;
                const int cl = ((k0 >> 3) + lsel + 4) ^ l7;
                LDSM_X4(ah[mf][0], ah[mf][1], ah[mf][2], ah[mf][3], rbase + ch * 16);
                LDSM_X4(al[mf][0], al[mf][1], al[mf][2], al[mf][3], rbase + cl * 16);
            }
#pragma unroll
            for (int np = 0; np < 2; np++) {
                const int rowN = wn + np * 16 + rowNl;
                const int ch = ((k0 >> 3) + ksel) ^ l7;
                const int cl = ((k0 >> 3) + ksel + 4) ^ l7;
                const uint32_t rb = bsb + (uint32_t)rowN * 128;
                uint32_t bh[4], bl[4];
                LDSM_X4(bh[0], bh[1], bh[2], bh[3], rb + ch * 16);
                LDSM_X4(bl[0], bl[1], bl[2], bl[3], rb + cl * 16);
#pragma unroll
                for (int mf = 0; mf < 2; mf++) {
                    MMA_BF16(acc[mf][2 * np], ah[mf][0], ah[mf][1], ah[mf][2], ah[mf][3], bh[0], bh[1]);
                    MMA_BF16(acc[mf][2 * np], al[mf][0], al[mf][1], al[mf][2], al[mf][3], bh[0], bh[1]);
                    MMA_BF16(acc[mf][2 * np], ah[mf][0], ah[mf][1], ah[mf][2], ah[mf][3], bl[0], bl[1]);
                    MMA_BF16(acc[mf][2 * np + 1], ah[mf][0], ah[mf][1], ah[mf][2], ah[mf][3], bh[2], bh[3]);
                    MMA_BF16(acc[mf][2 * np + 1], al[mf][0], al[mf][1], al[mf][2], al[mf][3], bh[2], bh[3]);
                    MMA_BF16(acc[mf][2 * np + 1], ah[mf][0], ah[mf][1], ah[mf][2], ah[mf][3], bl[2], bl[3]);
                }
            }
        }

        if (kt + 1 < GNT) {
            const int nxt = cur ^ 1;
            __syncthreads();
            As4[nxt][arow][akseg ^ am7] = pah0;
            As4[nxt][arow][(akseg + 4) ^ am7] = pal0;
            As4[nxt][arow + 64][akseg ^ am7] = pah1;
            As4[nxt][arow + 64][(akseg + 4) ^ am7] = pal1;
            Bs4[nxt][bnrow][bc ^ bn7] = u0;
            Bs4[nxt][bnrow + 32][bc ^ bn7] = u1;
            __syncthreads();
        }
    }

    // Epilogue: + bias + skip
#pragma unroll
    for (int mf = 0; mf < 2; mf++) {
        const int o = otile + wm + mf * 16 + g;
        const float b0v = bdep[o], b1v = bdep[o + 8];
        const size_t base = (size_t)b * CNsz + (size_t)o * Nn + noff + wn + tc * 2;
#pragma unroll
        for (int nf = 0; nf < 4; nf++) {
            const size_t i0 = base + nf * 8;
            float2 x0 = *(const float2*)(x_ori + i0);
            float2 x1 = *(const float2*)(x_ori + i0 + 8 * Nn);
            *(float2*)(out + i0) =
                make_float2(acc[mf][nf][0] + b0v + x0.x, acc[mf][nf][1] + b0v + x0.y);
            *(float2*)(out + i0 + 8 * Nn) =
                make_float2(acc[mf][nf][2] + b1v + x1.x, acc[mf][nf][3] + b1v + x1.y);
        }
    }
}

// ============================================================================
// Launch
// ============================================================================
extern "C" void kernel_launch(void* const* d_in, const int* in_sizes, int n_in,
                              void* d_out, int out_size)
{
    (void)in_sizes; (void)n_in; (void)out_size;
    const float* x_ori  = (const float*)d_in[0];
    const float* cross  = (const float*)d_in[1];
    const float* W_proj = (const float*)d_in[2];
    const float* b_proj = (const float*)d_in[3];
    const float* W_dep  = (const float*)d_in[4];
    const float* b_dep  = (const float*)d_in[5];
    float* out = (float*)d_out;

    k_split_all<<<2688, 256>>>(W_proj, W_dep, cross);
    k_proj_mma<<<dim3(32, 6), 256>>>(b_proj);
    k_mpart<<<dim3(Hh, Bb), 256>>>(cross);
    k_out<<<dim3(Bb * Hh, 4), 256>>>(x_ori);
    k_deproj_mma<<<dim3(32, 6), 256>>>(b_dep, x_ori, out);
}

// round 12
// speedup vs baseline: 1.2948x; 1.0192x over previous
#include <cuda_runtime.h>
#include <cuda_bf16.h>
#include <cstdint>

// Problem constants
#define Bb   8
#define Cc   768
#define Nn   256
#define Hh   12
#define Dd   64
#define HN   3072          // Hh*Nn
#define CNsz 196608        // Cc*Nn
#define SCALE 0.125f       // D^-0.5
#define GNT  24            // K tiles of 32 (K = 768)

// Scratch (allocation-free: __device__ globals)
__device__ __align__(16) float g_cp[Bb * CNsz];                // proj out [B,C,N]
__device__ __align__(16) float g_Mpart[Bb * Hh * Dd * Dd];     // per-(b,h) 64x64
__device__ __align__(16) float g_M[Bb * Dd * Dd];              // per-b 64x64
__device__ __align__(16) __nv_bfloat16 g_Uhi[Bb * Nn * Cc];    // U hi [B,N,C]
__device__ __align__(16) __nv_bfloat16 g_Ulo[Bb * Nn * Cc];    // U lo [B,N,C]

// ---- packed f32x2 helpers (for k_mpart) ----
#define FMA_F32X2(d, a, b, c) \
    asm("fma.rn.f32x2 %0, %1, %2, %3;" : "=l"(d) : "l"(a), "l"(b), "l"(c))

static __device__ __forceinline__ unsigned long long splat2(float x) {
    unsigned long long r;
    unsigned u = __float_as_uint(x);
    asm("mov.b64 %0, {%1, %1};" : "=l"(r) : "r"(u));
    return r;
}
static __device__ __forceinline__ float2 unpack2(unsigned long long v) {
    unsigned lo, hi;
    asm("mov.b64 {%0, %1}, %2;" : "=r"(lo), "=r"(hi) : "l"(v));
    return make_float2(__uint_as_float(lo), __uint_as_float(hi));
}

// ---- tensor-core primitives ----
static __device__ __forceinline__ uint32_t smem_u32(const void* p) {
    return (uint32_t)__cvta_generic_to_shared(p);
}

#define LDSM_X4(r0, r1, r2, r3, addr) \
    asm volatile("ldmatrix.sync.aligned.m8n8.x4.shared.b16 {%0,%1,%2,%3}, [%4];" \
        : "=r"(r0), "=r"(r1), "=r"(r2), "=r"(r3) : "r"(addr))

#define LDSM_X4_T(r0, r1, r2, r3, addr) \
    asm volatile("ldmatrix.sync.aligned.m8n8.x4.trans.shared.b16 {%0,%1,%2,%3}, [%4];" \
        : "=r"(r0), "=r"(r1), "=r"(r2), "=r"(r3) : "r"(addr))

#define MMA_BF16(D, a0, a1, a2, a3, b0, b1) \
    asm volatile("mma.sync.aligned.m16n8k16.row.col.f32.bf16.bf16.f32 " \
        "{%0,%1,%2,%3}, {%4,%5,%6,%7}, {%8,%9}, {%0,%1,%2,%3};" \
        : "+f"((D)[0]), "+f"((D)[1]), "+f"((D)[2]), "+f"((D)[3]) \
        : "r"(a0), "r"(a1), "r"(a2), "r"(a3), "r"(b0), "r"(b1))

// Split 8 fp32 -> bf16 hi chunk (16B) + bf16 lo chunk (16B)
static __device__ __forceinline__ void split8(float4 u, float4 v, uint4& hi, uint4& lo) {
    float f[8] = {u.x, u.y, u.z, u.w, v.x, v.y, v.z, v.w};
    uint32_t hw[4], lw[4];
#pragma unroll
    for (int i = 0; i < 4; i++) {
        __nv_bfloat16 h0 = __float2bfloat16(f[2 * i]);
        __nv_bfloat16 h1 = __float2bfloat16(f[2 * i + 1]);
        __nv_bfloat16 l0 = __float2bfloat16(f[2 * i] - __bfloat162float(h0));
        __nv_bfloat16 l1 = __float2bfloat16(f[2 * i + 1] - __bfloat162float(h1));
        __nv_bfloat162 hh(h0, h1), ll(l0, l1);
        hw[i] = *reinterpret_cast<uint32_t*>(&hh);
        lw[i] = *reinterpret_cast<uint32_t*>(&ll);
    }
    hi = make_uint4(hw[0], hw[1], hw[2], hw[3]);
    lo = make_uint4(lw[0], lw[1], lw[2], lw[3]);
}

// ============================================================================
// Kernel 1: cp = W_proj @ cross + b_proj, bf16 3-split tensor core.
// Block tile 128(o) x 64(n), BK=32, double-buffered smem, 1 barrier/tile.
// Grid (32, 6) = 192 blocks; 2 blocks/SM. (101.1us winner, verbatim.)
// ============================================================================
__global__ __launch_bounds__(256, 2) void k_proj_mma(
    const float* __restrict__ W, const float* __restrict__ cross,
    const float* __restrict__ bias)
{
    __shared__ uint4 As4[2][128][8];   // [buf][m][chunk 0-3 hi / 4-7 lo], XOR swizzle
    __shared__ uint4 Bs4[2][64][8];    // [buf][k 0-31 hi / 32-63 lo][n chunk]
    const int tid = threadIdx.x;
    const int wid = tid >> 5, lane = tid & 31;
    const int b = blockIdx.x >> 2;
    const int noff = (blockIdx.x & 3) * 64;
    const int otile = blockIdx.y * 128;

    const int wm = (wid >> 1) * 32;   // 0,32,64,96
    const int wn = (wid & 1) * 32;    // 0,32
    const int l7 = lane & 7, l15 = lane & 15, lsel = lane >> 4;
    const int g = lane >> 2, tc = lane & 3;

    const int arow = tid >> 2, akseg = tid & 3;    // A rows arow, arow+64
    const int am7 = arow & 7;
    const int bkrow = tid >> 3, bnseg = tid & 7;   // B k-row, n chunk
    const int bk7 = bkrow & 7;

    const float* Agp = W + (size_t)(otile + arow) * Cc + akseg * 8;
    const float* Bgp = cross + (size_t)b * CNsz + (size_t)bkrow * Nn + noff + bnseg * 8;

    const uint32_t as_base = smem_u32(&As4[0][0][0]);
    const uint32_t bs_base = smem_u32(&Bs4[0][0][0]);

    float acc[2][4][4];
#pragma unroll
    for (int i = 0; i < 2; i++)
#pragma unroll
        for (int j = 0; j < 4; j++)
#pragma unroll
            for (int e = 0; e < 4; e++) acc[i][j][e] = 0.f;

    float4 a0[2], a1[2], bv[2];
    a0[0] = *(const float4*)(Agp);
    a0[1] = *(const float4*)(Agp + 4);
    a1[0] = *(const float4*)(Agp + (size_t)64 * Cc);
    a1[1] = *(const float4*)(Agp + (size_t)64 * Cc + 4);
    bv[0] = *(const float4*)(Bgp);
    bv[1] = *(const float4*)(Bgp + 4);

    {
        uint4 h, l;
        split8(a0[0], a0[1], h, l);
        As4[0][arow][akseg ^ am7] = h;
        As4[0][arow][(akseg + 4) ^ am7] = l;
        split8(a1[0], a1[1], h, l);
        As4[0][arow + 64][akseg ^ am7] = h;
        As4[0][arow + 64][(akseg + 4) ^ am7] = l;
        split8(bv[0], bv[1], h, l);
        Bs4[0][bkrow][bnseg ^ bk7] = h;
        Bs4[0][bkrow + 32][bnseg ^ bk7] = l;
    }
    __syncthreads();

    for (int kt = 0; kt < GNT; kt++) {
        const int cur = kt & 1;
        if (kt + 1 < GNT) {
            Agp += 32;
            Bgp += (size_t)32 * Nn;
            a0[0] = *(const float4*)(Agp);
            a0[1] = *(const float4*)(Agp + 4);
            a1[0] = *(const float4*)(Agp + (size_t)64 * Cc);
            a1[1] = *(const float4*)(Agp + (size_t)64 * Cc + 4);
            bv[0] = *(const float4*)(Bgp);
            bv[1] = *(const float4*)(Bgp + 4);
        }

        const uint32_t asb = as_base + (uint32_t)cur * 16384;
        const uint32_t bsb = bs_base + (uint32_t)cur * 8192;
#pragma unroll
        for (int ks = 0; ks < 2; ks++) {
            const int k0 = ks * 16;
            uint32_t ah[2][4], al[2][4];
#pragma unroll
            for (int mf = 0; mf < 2; mf++) {
                const uint32_t rbase = asb + (uint32_t)(wm + mf * 16 + l15) * 128;
                const int ch = ((k0 >> 3) + lsel) ^ l7;
                const int cl = ((k0 >> 3) + lsel + 4) ^ l7;
                LDSM_X4(ah[mf][0], ah[mf][1], ah[mf][2], ah[mf][3], rbase + ch * 16);
                LDSM_X4(al[mf][0], al[mf][1], al[mf][2], al[mf][3], rbase + cl * 16);
            }
#pragma unroll
            for (int np = 0; np < 2; np++) {
                const int c = (wn >> 3) + np * 2 + lsel;
                const int p = c ^ l7;
                const uint32_t rb = bsb + (uint32_t)(k0 + l15) * 128 + p * 16;
                uint32_t bh[4], bl[4];
                LDSM_X4_T(bh[0], bh[1], bh[2], bh[3], rb);
                LDSM_X4_T(bl[0], bl[1], bl[2], bl[3], rb + 32 * 128);
#pragma unroll
                for (int mf = 0; mf < 2; mf++) {
                    MMA_BF16(acc[mf][2 * np], ah[mf][0], ah[mf][1], ah[mf][2], ah[mf][3], bh[0], bh[1]);
                    MMA_BF16(acc[mf][2 * np], al[mf][0], al[mf][1], al[mf][2], al[mf][3], bh[0], bh[1]);
                    MMA_BF16(acc[mf][2 * np], ah[mf][0], ah[mf][1], ah[mf][2], ah[mf][3], bl[0], bl[1]);
                    MMA_BF16(acc[mf][2 * np + 1], ah[mf][0], ah[mf][1], ah[mf][2], ah[mf][3], bh[2], bh[3]);
                    MMA_BF16(acc[mf][2 * np + 1], al[mf][0], al[mf][1], al[mf][2], al[mf][3], bh[2], bh[3]);
                    MMA_BF16(acc[mf][2 * np + 1], ah[mf][0], ah[mf][1], ah[mf][2], ah[mf][3], bl[2], bl[3]);
                }
            }
        }

        if (kt + 1 < GNT) {
            const int nxt = cur ^ 1;
            uint4 h, l;
            split8(a0[0], a0[1], h, l);
            As4[nxt][arow][akseg ^ am7] = h;
            As4[nxt][arow][(akseg + 4) ^ am7] = l;
            split8(a1[0], a1[1], h, l);
            As4[nxt][arow + 64][akseg ^ am7] = h;
            As4[nxt][arow + 64][(akseg + 4) ^ am7] = l;
            split8(bv[0], bv[1], h, l);
            Bs4[nxt][bkrow][bnseg ^ bk7] = h;
            Bs4[nxt][bkrow + 32][bnseg ^ bk7] = l;
            __syncthreads();
        }
    }

    // Epilogue: cp[o][n] + bias
#pragma unroll
    for (int mf = 0; mf < 2; mf++) {
        const int o = otile + wm + mf * 16 + g;
        const float b0v = bias[o], b1v = bias[o + 8];
        float* base = g_cp + (size_t)b * CNsz + (size_t)o * Nn + noff + wn + tc * 2;
#pragma unroll
        for (int nf = 0; nf < 4; nf++) {
            *(float2*)(base + nf * 8) =
                make_float2(acc[mf][nf][0] + b0v, acc[mf][nf][1] + b0v);
            *(float2*)(base + nf * 8 + 8 * Nn) =
                make_float2(acc[mf][nf][2] + b1v, acc[mf][nf][3] + b1v);
        }
    }
}

// ============================================================================
// Kernel 2: Mpart[b,h][d,d'] = sum_n cp[b,d*H+h,n] * cross[b,d'*H+h,n]
// One block per (b,h); f32x2 4x4 micro. (101.1us winner, verbatim.)
// ============================================================================
__global__ __launch_bounds__(256) void k_mpart(const float* __restrict__ cross)
{
    __shared__ float As[16][64];
    __shared__ float Bs[16][64];
    const int h = blockIdx.x;
    const int b = blockIdx.y;
    const int tid = threadIdx.x;
    const int r = tid >> 4, c = tid & 15;
    const int lr = tid >> 2, lk = (tid & 3) * 4;

    const float* Ab = g_cp + (size_t)b * CNsz + h * Nn;
    const float* Bp = cross + (size_t)b * CNsz + h * Nn;

    unsigned long long acc[4][2];
#pragma unroll
    for (int i = 0; i < 4; i++) { acc[i][0] = 0ull; acc[i][1] = 0ull; }

    for (int k0 = 0; k0 < Nn; k0 += 16) {
        float4 av = *(const float4*)(Ab + (size_t)lr * HN + k0 + lk);
        float4 bv = *(const float4*)(Bp + (size_t)lr * HN + k0 + lk);
        __syncthreads();
        As[lk + 0][lr] = av.x; As[lk + 1][lr] = av.y;
        As[lk + 2][lr] = av.z; As[lk + 3][lr] = av.w;
        Bs[lk + 0][lr] = bv.x; Bs[lk + 1][lr] = bv.y;
        Bs[lk + 2][lr] = bv.z; Bs[lk + 3][lr] = bv.w;
        __syncthreads();
#pragma unroll
        for (int k = 0; k < 16; k++) {
            float4 ar = *(const float4*)&As[k][r * 4];
            ulonglong2 bp = *(const ulonglong2*)&Bs[k][c * 4];
            unsigned long long sv;
            sv = splat2(ar.x);
            FMA_F32X2(acc[0][0], sv, bp.x, acc[0][0]);
            FMA_F32X2(acc[0][1], sv, bp.y, acc[0][1]);
            sv = splat2(ar.y);
            FMA_F32X2(acc[1][0], sv, bp.x, acc[1][0]);
            FMA_F32X2(acc[1][1], sv, bp.y, acc[1][1]);
            sv = splat2(ar.z);
            FMA_F32X2(acc[2][0], sv, bp.x, acc[2][0]);
            FMA_F32X2(acc[2][1], sv, bp.y, acc[2][1]);
            sv = splat2(ar.w);
            FMA_F32X2(acc[3][0], sv, bp.x, acc[3][0]);
            FMA_F32X2(acc[3][1], sv, bp.y, acc[3][1]);
        }
    }

    float* mp = g_Mpart + ((size_t)b * Hh + h) * 4096;
#pragma unroll
    for (int i = 0; i < 4; i++) {
        float2 lo = unpack2(acc[i][0]);
        float2 hi = unpack2(acc[i][1]);
        *(float4*)(mp + (size_t)(r * 4 + i) * 64 + c * 4) =
            make_float4(lo.x, lo.y, hi.x, hi.y);
    }
}

// ============================================================================
// Kernel 2b: M[b] = sum_h Mpart[b,h]. 128 blocks x 256 threads.
// ============================================================================
__global__ __launch_bounds__(256) void k_mred()
{
    const int idx = blockIdx.x * 256 + threadIdx.x;   // 32768
    const int b = idx >> 12;
    const int e = idx & 4095;
    float s = 0.f;
#pragma unroll
    for (int h = 0; h < Hh; h++)
        s += g_Mpart[((size_t)b * Hh + h) * 4096 + e];
    g_M[(size_t)b * 4096 + e] = s;
}

// ============================================================================
// Kernel 3: U rows = scale * x-row(m) . M[b], coalesced smem-staged version.
// Block = (b, hp) x n-half, 128 threads, thread = one n column.
// M[b] (16KB) resident in smem; x rows staged 8-at-a-time, double-buffered,
// fully coalesced. Emits bf16 hi/lo planes [b][n][C]. Grid (96, 2).
// ============================================================================
__global__ __launch_bounds__(128) void k_out(const float* __restrict__ x_ori)
{
    __shared__ float Ms[64][64];       // 16KB
    __shared__ float Xs[2][8][128];    // 2 x 4KB
    const int b = blockIdx.x / Hh;
    const int hp = blockIdx.x % Hh;
    const int s = blockIdx.y;
    const int tid = threadIdx.x;

    // load M[b]: 4096 floats, 8 float4 per thread, coalesced
    {
        const float4* src = (const float4*)(g_M + (size_t)b * 4096);
        float4* dst = (float4*)&Ms[0][0];
#pragma unroll
        for (int i = 0; i < 8; i++) dst[tid + i * 128] = src[tid + i * 128];
    }

    // staging geometry: row sr (0..7), cols sc..sc+7 of the 128-wide half
    const int sr = tid >> 4, sc = (tid & 15) * 8;
    const float* xb = x_ori + (size_t)b * CNsz + (size_t)hp * Nn + s * 128;

    float4 nx0, nx1;
    {
        const float* src = xb + (size_t)sr * HN + sc;
        nx0 = *(const float4*)(src);
        nx1 = *(const float4*)(src + 4);
    }

    float4 acc[16];
#pragma unroll
    for (int e = 0; e < 16; e++) acc[e] = make_float4(0.f, 0.f, 0.f, 0.f);

    for (int d0 = 0; d0 < 64; d0 += 8) {
        const int buf = (d0 >> 3) & 1;
        *(float4*)&Xs[buf][sr][sc] = nx0;
        *(float4*)&Xs[buf][sr][sc + 4] = nx1;
        __syncthreads();
        if (d0 + 8 < 64) {
            const float* src = xb + (size_t)(d0 + 8 + sr) * HN + sc;
            nx0 = *(const float4*)(src);
            nx1 = *(const float4*)(src + 4);
        }
        float xr[8];
#pragma unroll
        for (int i = 0; i < 8; i++) xr[i] = Xs[buf][i][tid];
#pragma unroll
        for (int i = 0; i < 8; i++) {
            const float4* Mr = (const float4*)&Ms[d0 + i][0];
            const float xv = xr[i];
#pragma unroll
            for (int e = 0; e < 16; e++) {
                float4 mv = Mr[e];
                acc[e].x += xv * mv.x;
                acc[e].y += xv * mv.y;
                acc[e].z += xv * mv.z;
                acc[e].w += xv * mv.w;
            }
        }
    }

    const int m = hp * Nn + s * 128 + tid;
    const int nf = m / Hh;
    const int hf = m - nf * Hh;
    const size_t off = ((size_t)b * Nn + nf) * Cc + hf * Dd;

    float v[64];
#pragma unroll
    for (int e = 0; e < 16; e++) *(float4*)&v[e * 4] = acc[e];
    uint32_t hw[32], lw[32];
#pragma unroll
    for (int i = 0; i < 32; i++) {
        float f0 = v[2 * i] * SCALE, f1 = v[2 * i + 1] * SCALE;
        __nv_bfloat16 h0 = __float2bfloat16(f0);
        __nv_bfloat16 h1 = __float2bfloat16(f1);
        __nv_bfloat16 l0 = __float2bfloat16(f0 - __bfloat162float(h0));
        __nv_bfloat16 l1 = __float2bfloat16(f1 - __bfloat162float(h1));
        __nv_bfloat162 hh(h0, h1), ll(l0, l1);
        hw[i] = *reinterpret_cast<uint32_t*>(&hh);
        lw[i] = *reinterpret_cast<uint32_t*>(&ll);
    }
#pragma unroll
    for (int q = 0; q < 4; q++) {
        *(uint4*)(g_Uhi + off + q * 16) =
            make_uint4(hw[q * 8 + 0], hw[q * 8 + 1], hw[q * 8 + 2], hw[q * 8 + 3]);
        *(uint4*)(g_Uhi + off + q * 16 + 8) =
            make_uint4(hw[q * 8 + 4], hw[q * 8 + 5], hw[q * 8 + 6], hw[q * 8 + 7]);
        *(uint4*)(g_Ulo + off + q * 16) =
            make_uint4(lw[q * 8 + 0], lw[q * 8 + 1], lw[q * 8 + 2], lw[q * 8 + 3]);
        *(uint4*)(g_Ulo + off + q * 16 + 8) =
            make_uint4(lw[q * 8 + 4], lw[q * 8 + 5], lw[q * 8 + 6], lw[q * 8 + 7]);
    }
}

// ============================================================================
// Kernel 4: out = x_ori + b_dep + U @ W_dep^T, bf16 3-split tensor core.
// 128x64 double-buffered skeleton; B pre-split by k_out. (101.1us winner.)
// ============================================================================
__global__ __launch_bounds__(256, 2) void k_deproj_mma(
    const float* __restrict__ Wdep, const float* __restrict__ bdep,
    const float* __restrict__ x_ori, float* __restrict__ out)
{
    __shared__ uint4 As4[2][128][8];   // [buf][o][chunk hi 0-3 / lo 4-7]
    __shared__ uint4 Bs4[2][64][8];    // [buf][n][chunk hi 0-3 / lo 4-7]
    const int tid = threadIdx.x;
    const int wid = tid >> 5, lane = tid & 31;
    const int b = blockIdx.x >> 2;
    const int noff = (blockIdx.x & 3) * 64;
    const int otile = blockIdx.y * 128;

    const int wm = (wid >> 1) * 32;
    const int wn = (wid & 1) * 32;
    const int l7 = lane & 7, l15 = lane & 15, lsel = lane >> 4;
    const int ksel = (lane >> 3) & 1;
    const int rowNl = (lane & 7) + (lsel << 3);
    const int g = lane >> 2, tc = lane & 3;

    const int arow = tid >> 2, akseg = tid & 3;
    const int am7 = arow & 7;
    const int bnrow = tid >> 3, bc = tid & 7;      // B: n-rows bnrow, bnrow+32
    const int bn7 = bnrow & 7;

    const float* Agp = Wdep + (size_t)(otile + arow) * Cc + akseg * 8;
    const __nv_bfloat16* Usrc = (bc < 4) ? g_Uhi : g_Ulo;
    const __nv_bfloat16* Ugp =
        Usrc + ((size_t)b * Nn + noff + bnrow) * Cc + (bc & 3) * 8;

    const uint32_t as_base = smem_u32(&As4[0][0][0]);
    const uint32_t bs_base = smem_u32(&Bs4[0][0][0]);

    float acc[2][4][4];
#pragma unroll
    for (int i = 0; i < 2; i++)
#pragma unroll
        for (int j = 0; j < 4; j++)
#pragma unroll
            for (int e = 0; e < 4; e++) acc[i][j][e] = 0.f;

    float4 a0[2], a1[2];
    uint4 u0, u1;
    a0[0] = *(const float4*)(Agp);
    a0[1] = *(const float4*)(Agp + 4);
    a1[0] = *(const float4*)(Agp + (size_t)64 * Cc);
    a1[1] = *(const float4*)(Agp + (size_t)64 * Cc + 4);
    u0 = *(const uint4*)(Ugp);
    u1 = *(const uint4*)(Ugp + (size_t)32 * Cc);

    {
        uint4 h, l;
        split8(a0[0], a0[1], h, l);
        As4[0][arow][akseg ^ am7] = h;
        As4[0][arow][(akseg + 4) ^ am7] = l;
        split8(a1[0], a1[1], h, l);
        As4[0][arow + 64][akseg ^ am7] = h;
        As4[0][arow + 64][(akseg + 4) ^ am7] = l;
        Bs4[0][bnrow][bc ^ bn7] = u0;
        Bs4[0][bnrow + 32][bc ^ bn7] = u1;
    }
    __syncthreads();

    for (int kt = 0; kt < GNT; kt++) {
        const int cur = kt & 1;
        if (kt + 1 < GNT) {
            Agp += 32;
            Ugp += 32;
            a0[0] = *(const float4*)(Agp);
            a0[1] = *(const float4*)(Agp + 4);
            a1[0] = *(const float4*)(Agp + (size_t)64 * Cc);
            a1[1] = *(const float4*)(Agp + (size_t)64 * Cc + 4);
            u0 = *(const uint4*)(Ugp);
            u1 = *(const uint4*)(Ugp + (size_t)32 * Cc);
        }

        const uint32_t asb = as_base + (uint32_t)cur * 16384;
        const uint32_t bsb = bs_base + (uint32_t)cur * 8192;
#pragma unroll
        for (int ks = 0; ks < 2; ks++) {
            const int k0 = ks * 16;
            uint32_t ah[2][4], al[2][4];
#pragma unroll
            for (int mf = 0; mf < 2; mf++) {
                const uint32_t rbase = asb + (uint32_t)(wm + mf * 16 + l15) * 128;
                const int ch = ((k0 >> 3) + lsel) ^ l7;
                const int cl = ((k0 >> 3) + lsel + 4) ^ l7;
                LDSM_X4(ah[mf][0], ah[mf][1], ah[mf][2], ah[mf][3], rbase + ch * 16);
                LDSM_X4(al[mf][0], al[mf][1], al[mf][2], al[mf][3], rbase + cl * 16);
            }
#pragma unroll
            for (int np = 0; np < 2; np++) {
                const int rowN = wn + np * 16 + rowNl;
                const int ch = ((k0 >> 3) + ksel) ^ l7;
                const int cl = ((k0 >> 3) + ksel + 4) ^ l7;
                const uint32_t rb = bsb + (uint32_t)rowN * 128;
                uint32_t bh[4], bl[4];
                LDSM_X4(bh[0], bh[1], bh[2], bh[3], rb + ch * 16);
                LDSM_X4(bl[0], bl[1], bl[2], bl[3], rb + cl * 16);
#pragma unroll
                for (int mf = 0; mf < 2; mf++) {
                    MMA_BF16(acc[mf][2 * np], ah[mf][0], ah[mf][1], ah[mf][2], ah[mf][3], bh[0], bh[1]);
                    MMA_BF16(acc[mf][2 * np], al[mf][0], al[mf][1], al[mf][2], al[mf][3], bh[0], bh[1]);
                    MMA_BF16(acc[mf][2 * np], ah[mf][0], ah[mf][1], ah[mf][2], ah[mf][3], bl[0], bl[1]);
                    MMA_BF16(acc[mf][2 * np + 1], ah[mf][0], ah[mf][1], ah[mf][2], ah[mf][3], bh[2], bh[3]);
                    MMA_BF16(acc[mf][2 * np + 1], al[mf][0], al[mf][1], al[mf][2], al[mf][3], bh[2], bh[3]);
                    MMA_BF16(acc[mf][2 * np + 1], ah[mf][0], ah[mf][1], ah[mf][2], ah[mf][3], bl[2], bl[3]);
                }
            }
        }

        if (kt + 1 < GNT) {
            const int nxt = cur ^ 1;
            uint4 h, l;
            split8(a0[0], a0[1], h, l);
            As4[nxt][arow][akseg ^ am7] = h;
            As4[nxt][arow][(akseg + 4) ^ am7] = l;
            split8(a1[0], a1[1], h, l);
            As4[nxt][arow + 64][akseg ^ am7] = h;
            As4[nxt][arow + 64][(akseg + 4) ^ am7] = l;
            Bs4[nxt][bnrow][bc ^ bn7] = u0;
            Bs4[nxt][bnrow + 32][bc ^ bn7] = u1;
            __syncthreads();
        }
    }

    // Epilogue: + bias + skip
#pragma unroll
    for (int mf = 0; mf < 2; mf++) {
        const int o = otile + wm + mf * 16 + g;
        const float b0v = bdep[o], b1v = bdep[o + 8];
        const size_t base = (size_t)b * CNsz + (size_t)o * Nn + noff + wn + tc * 2;
#pragma unroll
        for (int nf = 0; nf < 4; nf++) {
            const size_t i0 = base + nf * 8;
            float2 x0 = *(const float2*)(x_ori + i0);
            float2 x1 = *(const float2*)(x_ori + i0 + 8 * Nn);
            *(float2*)(out + i0) =
                make_float2(acc[mf][nf][0] + b0v + x0.x, acc[mf][nf][1] + b0v + x0.y);
            *(float2*)(out + i0 + 8 * Nn) =
                make_float2(acc[mf][nf][2] + b1v + x1.x, acc[mf][nf][3] + b1v + x1.y);
        }
    }
}

// ============================================================================
// Launch
// ============================================================================
extern "C" void kernel_launch(void* const* d_in, const int* in_sizes, int n_in,
                              void* d_out, int out_size)
{
    (void)in_sizes; (void)n_in; (void)out_size;
    const float* x_ori  = (const float*)d_in[0];
    const float* cross  = (const float*)d_in[1];
    const float* W_proj = (const float*)d_in[2];
    const float* b_proj = (const float*)d_in[3];
    const float* W_dep  = (const float*)d_in[4];
    const float* b_dep  = (const float*)d_in[5];
    float* out = (float*)d_out;

    k_proj_mma<<<dim3(32, 6), 256>>>(W_proj, cross, b_proj);
    k_mpart<<<dim3(Hh, Bb), 256>>>(cross);
    k_mred<<<128, 256>>>();
    k_out<<<dim3(Bb * Hh, 2), 128>>>(x_ori);
    k_deproj_mma<<<dim3(32, 6), 256>>>(W_dep, b_dep, x_ori, out);
}

// round 13
// speedup vs baseline: 1.3247x; 1.0231x over previous
#include <cuda_runtime.h>
#include <cuda_bf16.h>
#include <cstdint>

// Problem constants
#define Bb   8
#define Cc   768
#define Nn   256
#define Hh   12
#define Dd   64
#define HN   3072          // Hh*Nn
#define CNsz 196608        // Cc*Nn
#define SCALE 0.125f       // D^-0.5
#define GNT  24            // K tiles of 32 (K = 768)

// Scratch (allocation-free: __device__ globals)
__device__ __align__(16) float g_cp[Bb * CNsz];                // proj out [B,C,N]
__device__ __align__(16) float g_Mpart[Bb * Hh * Dd * Dd];     // per-(b,h) 64x64
__device__ __align__(16) float g_M[Bb * Dd * Dd];              // per-b 64x64 (pre-scaled)
__device__ __align__(16) __nv_bfloat16 g_Uhi[Bb * Nn * Cc];    // U hi [B,N,C]
__device__ __align__(16) __nv_bfloat16 g_Ulo[Bb * Nn * Cc];    // U lo [B,N,C]

// ---- packed f32x2 helpers ----
#define FMA_F32X2(d, a, b, c) \
    asm("fma.rn.f32x2 %0, %1, %2, %3;" : "=l"(d) : "l"(a), "l"(b), "l"(c))

static __device__ __forceinline__ unsigned long long splat2(float x) {
    unsigned long long r;
    unsigned u = __float_as_uint(x);
    asm("mov.b64 %0, {%1, %1};" : "=l"(r) : "r"(u));
    return r;
}
static __device__ __forceinline__ float2 unpack2(unsigned long long v) {
    unsigned lo, hi;
    asm("mov.b64 {%0, %1}, %2;" : "=r"(lo), "=r"(hi) : "l"(v));
    return make_float2(__uint_as_float(lo), __uint_as_float(hi));
}

// ---- tensor-core primitives ----
static __device__ __forceinline__ uint32_t smem_u32(const void* p) {
    return (uint32_t)__cvta_generic_to_shared(p);
}

#define LDSM_X4(r0, r1, r2, r3, addr) \
    asm volatile("ldmatrix.sync.aligned.m8n8.x4.shared.b16 {%0,%1,%2,%3}, [%4];" \
        : "=r"(r0), "=r"(r1), "=r"(r2), "=r"(r3) : "r"(addr))

#define LDSM_X4_T(r0, r1, r2, r3, addr) \
    asm volatile("ldmatrix.sync.aligned.m8n8.x4.trans.shared.b16 {%0,%1,%2,%3}, [%4];" \
        : "=r"(r0), "=r"(r1), "=r"(r2), "=r"(r3) : "r"(addr))

#define MMA_BF16(D, a0, a1, a2, a3, b0, b1) \
    asm volatile("mma.sync.aligned.m16n8k16.row.col.f32.bf16.bf16.f32 " \
        "{%0,%1,%2,%3}, {%4,%5,%6,%7}, {%8,%9}, {%0,%1,%2,%3};" \
        : "+f"((D)[0]), "+f"((D)[1]), "+f"((D)[2]), "+f"((D)[3]) \
        : "r"(a0), "r"(a1), "r"(a2), "r"(a3), "r"(b0), "r"(b1))

// Split 8 fp32 -> bf16 hi chunk (16B) + bf16 lo chunk (16B)
static __device__ __forceinline__ void split8(float4 u, float4 v, uint4& hi, uint4& lo) {
    float f[8] = {u.x, u.y, u.z, u.w, v.x, v.y, v.z, v.w};
    uint32_t hw[4], lw[4];
#pragma unroll
    for (int i = 0; i < 4; i++) {
        __nv_bfloat16 h0 = __float2bfloat16(f[2 * i]);
        __nv_bfloat16 h1 = __float2bfloat16(f[2 * i + 1]);
        __nv_bfloat16 l0 = __float2bfloat16(f[2 * i] - __bfloat162float(h0));
        __nv_bfloat16 l1 = __float2bfloat16(f[2 * i + 1] - __bfloat162float(h1));
        __nv_bfloat162 hh(h0, h1), ll(l0, l1);
        hw[i] = *reinterpret_cast<uint32_t*>(&hh);
        lw[i] = *reinterpret_cast<uint32_t*>(&ll);
    }
    hi = make_uint4(hw[0], hw[1], hw[2], hw[3]);
    lo = make_uint4(lw[0], lw[1], lw[2], lw[3]);
}

// ============================================================================
// Kernel 1: cp = W_proj @ cross + b_proj, bf16 3-split tensor core.
// Block tile 128(o) x 64(n), BK=32, double-buffered smem, 1 barrier/tile.
// Grid (32, 6) = 192 blocks; 2 blocks/SM. (101.1us winner, verbatim.)
// ============================================================================
__global__ __launch_bounds__(256, 2) void k_proj_mma(
    const float* __restrict__ W, const float* __restrict__ cross,
    const float* __restrict__ bias)
{
    __shared__ uint4 As4[2][128][8];   // [buf][m][chunk 0-3 hi / 4-7 lo], XOR swizzle
    __shared__ uint4 Bs4[2][64][8];    // [buf][k 0-31 hi / 32-63 lo][n chunk]
    const int tid = threadIdx.x;
    const int wid = tid >> 5, lane = tid & 31;
    const int b = blockIdx.x >> 2;
    const int noff = (blockIdx.x & 3) * 64;
    const int otile = blockIdx.y * 128;

    const int wm = (wid >> 1) * 32;   // 0,32,64,96
    const int wn = (wid & 1) * 32;    // 0,32
    const int l7 = lane & 7, l15 = lane & 15, lsel = lane >> 4;
    const int g = lane >> 2, tc = lane & 3;

    const int arow = tid >> 2, akseg = tid & 3;    // A rows arow, arow+64
    const int am7 = arow & 7;
    const int bkrow = tid >> 3, bnseg = tid & 7;   // B k-row, n chunk
    const int bk7 = bkrow & 7;

    const float* Agp = W + (size_t)(otile + arow) * Cc + akseg * 8;
    const float* Bgp = cross + (size_t)b * CNsz + (size_t)bkrow * Nn + noff + bnseg * 8;

    const uint32_t as_base = smem_u32(&As4[0][0][0]);
    const uint32_t bs_base = smem_u32(&Bs4[0][0][0]);

    float acc[2][4][4];
#pragma unroll
    for (int i = 0; i < 2; i++)
#pragma unroll
        for (int j = 0; j < 4; j++)
#pragma unroll
            for (int e = 0; e < 4; e++) acc[i][j][e] = 0.f;

    float4 a0[2], a1[2], bv[2];
    a0[0] = *(const float4*)(Agp);
    a0[1] = *(const float4*)(Agp + 4);
    a1[0] = *(const float4*)(Agp + (size_t)64 * Cc);
    a1[1] = *(const float4*)(Agp + (size_t)64 * Cc + 4);
    bv[0] = *(const float4*)(Bgp);
    bv[1] = *(const float4*)(Bgp + 4);

    {
        uint4 h, l;
        split8(a0[0], a0[1], h, l);
        As4[0][arow][akseg ^ am7] = h;
        As4[0][arow][(akseg + 4) ^ am7] = l;
        split8(a1[0], a1[1], h, l);
        As4[0][arow + 64][akseg ^ am7] = h;
        As4[0][arow + 64][(akseg + 4) ^ am7] = l;
        split8(bv[0], bv[1], h, l);
        Bs4[0][bkrow][bnseg ^ bk7] = h;
        Bs4[0][bkrow + 32][bnseg ^ bk7] = l;
    }
    __syncthreads();

    for (int kt = 0; kt < GNT; kt++) {
        const int cur = kt & 1;
        if (kt + 1 < GNT) {
            Agp += 32;
            Bgp += (size_t)32 * Nn;
            a0[0] = *(const float4*)(Agp);
            a0[1] = *(const float4*)(Agp + 4);
            a1[0] = *(const float4*)(Agp + (size_t)64 * Cc);
            a1[1] = *(const float4*)(Agp + (size_t)64 * Cc + 4);
            bv[0] = *(const float4*)(Bgp);
            bv[1] = *(const float4*)(Bgp + 4);
        }

        const uint32_t asb = as_base + (uint32_t)cur * 16384;
        const uint32_t bsb = bs_base + (uint32_t)cur * 8192;
#pragma unroll
        for (int ks = 0; ks < 2; ks++) {
            const int k0 = ks * 16;
            uint32_t ah[2][4], al[2][4];
#pragma unroll
            for (int mf = 0; mf < 2; mf++) {
                const uint32_t rbase = asb + (uint32_t)(wm + mf * 16 + l15) * 128;
                const int ch = ((k0 >> 3) + lsel) ^ l7;
                const int cl = ((k0 >> 3) + lsel + 4) ^ l7;
                LDSM_X4(ah[mf][0], ah[mf][1], ah[mf][2], ah[mf][3], rbase + ch * 16);
                LDSM_X4(al[mf][0], al[mf][1], al[mf][2], al[mf][3], rbase + cl * 16);
            }
#pragma unroll
            for (int np = 0; np < 2; np++) {
                const int c = (wn >> 3) + np * 2 + lsel;
                const int p = c ^ l7;
                const uint32_t rb = bsb + (uint32_t)(k0 + l15) * 128 + p * 16;
                uint32_t bh[4], bl[4];
                LDSM_X4_T(bh[0], bh[1], bh[2], bh[3], rb);
                LDSM_X4_T(bl[0], bl[1], bl[2], bl[3], rb + 32 * 128);
#pragma unroll
                for (int mf = 0; mf < 2; mf++) {
                    MMA_BF16(acc[mf][2 * np], ah[mf][0], ah[mf][1], ah[mf][2], ah[mf][3], bh[0], bh[1]);
                    MMA_BF16(acc[mf][2 * np], al[mf][0], al[mf][1], al[mf][2], al[mf][3], bh[0], bh[1]);
                    MMA_BF16(acc[mf][2 * np], ah[mf][0], ah[mf][1], ah[mf][2], ah[mf][3], bl[0], bl[1]);
                    MMA_BF16(acc[mf][2 * np + 1], ah[mf][0], ah[mf][1], ah[mf][2], ah[mf][3], bh[2], bh[3]);
                    MMA_BF16(acc[mf][2 * np + 1], al[mf][0], al[mf][1], al[mf][2], al[mf][3], bh[2], bh[3]);
                    MMA_BF16(acc[mf][2 * np + 1], ah[mf][0], ah[mf][1], ah[mf][2], ah[mf][3], bl[2], bl[3]);
                }
            }
        }

        if (kt + 1 < GNT) {
            const int nxt = cur ^ 1;
            uint4 h, l;
            split8(a0[0], a0[1], h, l);
            As4[nxt][arow][akseg ^ am7] = h;
            As4[nxt][arow][(akseg + 4) ^ am7] = l;
            split8(a1[0], a1[1], h, l);
            As4[nxt][arow + 64][akseg ^ am7] = h;
            As4[nxt][arow + 64][(akseg + 4) ^ am7] = l;
            split8(bv[0], bv[1], h, l);
            Bs4[nxt][bkrow][bnseg ^ bk7] = h;
            Bs4[nxt][bkrow + 32][bnseg ^ bk7] = l;
            __syncthreads();
        }
    }

    // Epilogue: cp[o][n] + bias
#pragma unroll
    for (int mf = 0; mf < 2; mf++) {
        const int o = otile + wm + mf * 16 + g;
        const float b0v = bias[o], b1v = bias[o + 8];
        float* base = g_cp + (size_t)b * CNsz + (size_t)o * Nn + noff + wn + tc * 2;
#pragma unroll
        for (int nf = 0; nf < 4; nf++) {
            *(float2*)(base + nf * 8) =
                make_float2(acc[mf][nf][0] + b0v, acc[mf][nf][1] + b0v);
            *(float2*)(base + nf * 8 + 8 * Nn) =
                make_float2(acc[mf][nf][2] + b1v, acc[mf][nf][3] + b1v);
        }
    }
}

// ============================================================================
// Kernel 2: Mpart[b,h][d,d'] = sum_n cp[b,d*H+h,n] * cross[b,d'*H+h,n]
// One block per (b,h); f32x2 4x4 micro. (101.1us winner, verbatim.)
// ============================================================================
__global__ __launch_bounds__(256) void k_mpart(const float* __restrict__ cross)
{
    __shared__ float As[16][64];
    __shared__ float Bs[16][64];
    const int h = blockIdx.x;
    const int b = blockIdx.y;
    const int tid = threadIdx.x;
    const int r = tid >> 4, c = tid & 15;
    const int lr = tid >> 2, lk = (tid & 3) * 4;

    const float* Ab = g_cp + (size_t)b * CNsz + h * Nn;
    const float* Bp = cross + (size_t)b * CNsz + h * Nn;

    unsigned long long acc[4][2];
#pragma unroll
    for (int i = 0; i < 4; i++) { acc[i][0] = 0ull; acc[i][1] = 0ull; }

    for (int k0 = 0; k0 < Nn; k0 += 16) {
        float4 av = *(const float4*)(Ab + (size_t)lr * HN + k0 + lk);
        float4 bv = *(const float4*)(Bp + (size_t)lr * HN + k0 + lk);
        __syncthreads();
        As[lk + 0][lr] = av.x; As[lk + 1][lr] = av.y;
        As[lk + 2][lr] = av.z; As[lk + 3][lr] = av.w;
        Bs[lk + 0][lr] = bv.x; Bs[lk + 1][lr] = bv.y;
        Bs[lk + 2][lr] = bv.z; Bs[lk + 3][lr] = bv.w;
        __syncthreads();
#pragma unroll
        for (int k = 0; k < 16; k++) {
            float4 ar = *(const float4*)&As[k][r * 4];
            ulonglong2 bp = *(const ulonglong2*)&Bs[k][c * 4];
            unsigned long long sv;
            sv = splat2(ar.x);
            FMA_F32X2(acc[0][0], sv, bp.x, acc[0][0]);
            FMA_F32X2(acc[0][1], sv, bp.y, acc[0][1]);
            sv = splat2(ar.y);
            FMA_F32X2(acc[1][0], sv, bp.x, acc[1][0]);
            FMA_F32X2(acc[1][1], sv, bp.y, acc[1][1]);
            sv = splat2(ar.z);
            FMA_F32X2(acc[2][0], sv, bp.x, acc[2][0]);
            FMA_F32X2(acc[2][1], sv, bp.y, acc[2][1]);
            sv = splat2(ar.w);
            FMA_F32X2(acc[3][0], sv, bp.x, acc[3][0]);
            FMA_F32X2(acc[3][1], sv, bp.y, acc[3][1]);
        }
    }

    float* mp = g_Mpart + ((size_t)b * Hh + h) * 4096;
#pragma unroll
    for (int i = 0; i < 4; i++) {
        float2 lo = unpack2(acc[i][0]);
        float2 hi = unpack2(acc[i][1]);
        *(float4*)(mp + (size_t)(r * 4 + i) * 64 + c * 4) =
            make_float4(lo.x, lo.y, hi.x, hi.y);
    }
}

// ============================================================================
// Kernel 2b: M[b] = SCALE * sum_h Mpart[b,h]. 128 blocks x 256 threads.
// ============================================================================
__global__ __launch_bounds__(256) void k_mred()
{
    const int idx = blockIdx.x * 256 + threadIdx.x;   // 32768
    const int b = idx >> 12;
    const int e = idx & 4095;
    float s = 0.f;
#pragma unroll
    for (int h = 0; h < Hh; h++)
        s += g_Mpart[((size_t)b * Hh + h) * 4096 + e];
    g_M[(size_t)b * 4096 + e] = s * SCALE;
}

// ============================================================================
// Kernel 3: U rows = x-row(m) . M[b] (M pre-scaled). f32x2 accumulation,
// d' split in halves. Block = (b,hp) x (s n-half, dq d'-half); 128 threads.
// Grid (96, 4) = 384 blocks; ~80 regs -> 3 blocks/SM. Coalesced X staging.
// ============================================================================
__global__ __launch_bounds__(128) void k_out(const float* __restrict__ x_ori)
{
    __shared__ float Ms[64][32];       // 8KB: M[b][d][dq*32 + c]
    __shared__ float Xs[2][8][128];    // 2 x 4KB
    const int b = blockIdx.x / Hh;
    const int hp = blockIdx.x % Hh;
    const int s = blockIdx.y >> 1;     // n half (128)
    const int dq = blockIdx.y & 1;     // d' half (32)
    const int tid = threadIdx.x;

    // load M half: 2048 floats, 4 float4/thread
    {
#pragma unroll
        for (int j = 0; j < 4; j++) {
            const int idx = tid + j * 128;          // 0..511 float4s
            const int d = idx >> 3, c4 = (idx & 7) * 4;
            *(float4*)&Ms[d][c4] =
                *(const float4*)(g_M + (size_t)b * 4096 + d * 64 + dq * 32 + c4);
        }
    }

    const int sr = tid >> 4, sc = (tid & 15) * 8;
    const float* xb = x_ori + (size_t)b * CNsz + (size_t)hp * Nn + s * 128;

    float4 nx0, nx1;
    {
        const float* src = xb + (size_t)sr * HN + sc;
        nx0 = *(const float4*)(src);
        nx1 = *(const float4*)(src + 4);
    }

    unsigned long long acc[16];
#pragma unroll
    for (int e = 0; e < 16; e++) acc[e] = 0ull;

    for (int d0 = 0; d0 < 64; d0 += 8) {
        const int buf = (d0 >> 3) & 1;
        *(float4*)&Xs[buf][sr][sc] = nx0;
        *(float4*)&Xs[buf][sr][sc + 4] = nx1;
        __syncthreads();
        if (d0 + 8 < 64) {
            const float* src = xb + (size_t)(d0 + 8 + sr) * HN + sc;
            nx0 = *(const float4*)(src);
            nx1 = *(const float4*)(src + 4);
        }
        float xr[8];
#pragma unroll
        for (int i = 0; i < 8; i++) xr[i] = Xs[buf][i][tid];
#pragma unroll
        for (int i = 0; i < 8; i++) {
            const ulonglong2* Mr = (const ulonglong2*)&Ms[d0 + i][0];
            const unsigned long long sv = splat2(xr[i]);
#pragma unroll
            for (int e2 = 0; e2 < 8; e2++) {
                ulonglong2 mp = Mr[e2];
                FMA_F32X2(acc[2 * e2], sv, mp.x, acc[2 * e2]);
                FMA_F32X2(acc[2 * e2 + 1], sv, mp.y, acc[2 * e2 + 1]);
            }
        }
    }

    const int m = hp * Nn + s * 128 + tid;
    const int nf = m / Hh;
    const int hf = m - nf * Hh;
    const size_t off = ((size_t)b * Nn + nf) * Cc + hf * Dd + dq * 32;

    uint32_t hw[16], lw[16];
#pragma unroll
    for (int i = 0; i < 16; i++) {
        float2 p = unpack2(acc[i]);
        __nv_bfloat16 h0 = __float2bfloat16(p.x);
        __nv_bfloat16 h1 = __float2bfloat16(p.y);
        __nv_bfloat16 l0 = __float2bfloat16(p.x - __bfloat162float(h0));
        __nv_bfloat16 l1 = __float2bfloat16(p.y - __bfloat162float(h1));
        __nv_bfloat162 hh(h0, h1), ll(l0, l1);
        hw[i] = *reinterpret_cast<uint32_t*>(&hh);
        lw[i] = *reinterpret_cast<uint32_t*>(&ll);
    }
#pragma unroll
    for (int q = 0; q < 2; q++) {
        *(uint4*)(g_Uhi + off + q * 16) =
            make_uint4(hw[q * 8 + 0], hw[q * 8 + 1], hw[q * 8 + 2], hw[q * 8 + 3]);
        *(uint4*)(g_Uhi + off + q * 16 + 8) =
            make_uint4(hw[q * 8 + 4], hw[q * 8 + 5], hw[q * 8 + 6], hw[q * 8 + 7]);
        *(uint4*)(g_Ulo + off + q * 16) =
            make_uint4(lw[q * 8 + 0], lw[q * 8 + 1], lw[q * 8 + 2], lw[q * 8 + 3]);
        *(uint4*)(g_Ulo + off + q * 16 + 8) =
            make_uint4(lw[q * 8 + 4], lw[q * 8 + 5], lw[q * 8 + 6], lw[q * 8 + 7]);
    }
}

// ============================================================================
// Kernel 4: out = x_ori + b_dep + U @ W_dep^T, bf16 3-split tensor core.
// 128x64 double-buffered skeleton; B pre-split by k_out. (101.1us winner.)
// ============================================================================
__global__ __launch_bounds__(256, 2) void k_deproj_mma(
    const float* __restrict__ Wdep, const float* __restrict__ bdep,
    const float* __restrict__ x_ori, float* __restrict__ out)
{
    __shared__ uint4 As4[2][128][8];   // [buf][o][chunk hi 0-3 / 4-7 lo]
    __shared__ uint4 Bs4[2][64][8];    // [buf][n][chunk hi 0-3 / 4-7 lo]
    const int tid = threadIdx.x;
    const int wid = tid >> 5, lane = tid & 31;
    const int b = blockIdx.x >> 2;
    const int noff = (blockIdx.x & 3) * 64;
    const int otile = blockIdx.y * 128;

    const int wm = (wid >> 1) * 32;
    const int wn = (wid & 1) * 32;
    const int l7 = lane & 7, l15 = lane & 15, lsel = lane >> 4;
    const int ksel = (lane >> 3) & 1;
    const int rowNl = (lane & 7) + (lsel << 3);
    const int g = lane >> 2, tc = lane & 3;

    const int arow = tid >> 2, akseg = tid & 3;
    const int am7 = arow & 7;
    const int bnrow = tid >> 3, bc = tid & 7;      // B: n-rows bnrow, bnrow+32
    const int bn7 = bnrow & 7;

    const float* Agp = Wdep + (size_t)(otile + arow) * Cc + akseg * 8;
    const __nv_bfloat16* Usrc = (bc < 4) ? g_Uhi : g_Ulo;
    const __nv_bfloat16* Ugp =
        Usrc + ((size_t)b * Nn + noff + bnrow) * Cc + (bc & 3) * 8;

    const uint32_t as_base = smem_u32(&As4[0][0][0]);
    const uint32_t bs_base = smem_u32(&Bs4[0][0][0]);

    float acc[2][4][4];
#pragma unroll
    for (int i = 0; i < 2; i++)
#pragma unroll
        for (int j = 0; j < 4; j++)
#pragma unroll
            for (int e = 0; e < 4; e++) acc[i][j][e] = 0.f;

    float4 a0[2], a1[2];
    uint4 u0, u1;
    a0[0] = *(const float4*)(Agp);
    a0[1] = *(const float4*)(Agp + 4);
    a1[0] = *(const float4*)(Agp + (size_t)64 * Cc);
    a1[1] = *(const float4*)(Agp + (size_t)64 * Cc + 4);
    u0 = *(const uint4*)(Ugp);
    u1 = *(const uint4*)(Ugp + (size_t)32 * Cc);

    {
        uint4 h, l;
        split8(a0[0], a0[1], h, l);
        As4[0][arow][akseg ^ am7] = h;
        As4[0][arow][(akseg + 4) ^ am7] = l;
        split8(a1[0], a1[1], h, l);
        As4[0][arow + 64][akseg ^ am7] = h;
        As4[0][arow + 64][(akseg + 4) ^ am7] = l;
        Bs4[0][bnrow][bc ^ bn7] = u0;
        Bs4[0][bnrow + 32][bc ^ bn7] = u1;
    }
    __syncthreads();

    for (int kt = 0; kt < GNT; kt++) {
        const int cur = kt & 1;
        if (kt + 1 < GNT) {
            Agp += 32;
            Ugp += 32;
            a0[0] = *(const float4*)(Agp);
            a0[1] = *(const float4*)(Agp + 4);
            a1[0] = *(const float4*)(Agp + (size_t)64 * Cc);
            a1[1] = *(const float4*)(Agp + (size_t)64 * Cc + 4);
            u0 = *(const uint4*)(Ugp);
            u1 = *(const uint4*)(Ugp + (size_t)32 * Cc);
        }

        const uint32_t asb = as_base + (uint32_t)cur * 16384;
        const uint32_t bsb = bs_base + (uint32_t)cur * 8192;
#pragma unroll
        for (int ks = 0; ks < 2; ks++) {
            const int k0 = ks * 16;
            uint32_t ah[2][4], al[2][4];
#pragma unroll
            for (int mf = 0; mf < 2; mf++) {
                const uint32_t rbase = asb + (uint32_t)(wm + mf * 16 + l15) * 128;
                const int ch = ((k0 >> 3) + lsel) ^ l7;
                const int cl = ((k0 >> 3) + lsel + 4) ^ l7;
                LDSM_X4(ah[mf][0], ah[mf][1], ah[mf][2], ah[mf][3], rbase + ch * 16);
                LDSM_X4(al[mf][0], al[mf][1], al[mf][2], al[mf][3], rbase + cl * 16);
            }
#pragma unroll
            for (int np = 0; np < 2; np++) {
                const int rowN = wn + np * 16 + rowNl;
                const int ch = ((k0 >> 3) + ksel) ^ l7;
                const int cl = ((k0 >> 3) + ksel + 4) ^ l7;
                const uint32_t rb = bsb + (uint32_t)rowN * 128;
                uint32_t bh[4], bl[4];
                LDSM_X4(bh[0], bh[1], bh[2], bh[3], rb + ch * 16);
                LDSM_X4(bl[0], bl[1], bl[2], bl[3], rb + cl * 16);
#pragma unroll
                for (int mf = 0; mf < 2; mf++) {
                    MMA_BF16(acc[mf][2 * np], ah[mf][0], ah[mf][1], ah[mf][2], ah[mf][3], bh[0], bh[1]);
                    MMA_BF16(acc[mf][2 * np], al[mf][0], al[mf][1], al[mf][2], al[mf][3], bh[0], bh[1]);
                    MMA_BF16(acc[mf][2 * np], ah[mf][0], ah[mf][1], ah[mf][2], ah[mf][3], bl[0], bl[1]);
                    MMA_BF16(acc[mf][2 * np + 1], ah[mf][0], ah[mf][1], ah[mf][2], ah[mf][3], bh[2], bh[3]);
                    MMA_BF16(acc[mf][2 * np + 1], al[mf][0], al[mf][1], al[mf][2], al[mf][3], bh[2], bh[3]);
                    MMA_BF16(acc[mf][2 * np + 1], ah[mf][0], ah[mf][1], ah[mf][2], ah[mf][3], bl[2], bl[3]);
                }
            }
        }

        if (kt + 1 < GNT) {
            const int nxt = cur ^ 1;
            uint4 h, l;
            split8(a0[0], a0[1], h, l);
            As4[nxt][arow][akseg ^ am7] = h;
            As4[nxt][arow][(akseg + 4) ^ am7] = l;
            split8(a1[0], a1[1], h, l);
            As4[nxt][arow + 64][akseg ^ am7] = h;
            As4[nxt][arow + 64][(akseg + 4) ^ am7] = l;
            Bs4[nxt][bnrow][bc ^ bn7] = u0;
            Bs4[nxt][bnrow + 32][bc ^ bn7] = u1;
            __syncthreads();
        }
    }

    // Epilogue: + bias + skip
#pragma unroll
    for (int mf = 0; mf < 2; mf++) {
        const int o = otile + wm + mf * 16 + g;
        const float b0v = bdep[o], b1v = bdep[o + 8];
        const size_t base = (size_t)b * CNsz + (size_t)o * Nn + noff + wn + tc * 2;
#pragma unroll
        for (int nf = 0; nf < 4; nf++) {
            const size_t i0 = base + nf * 8;
            float2 x0 = *(const float2*)(x_ori + i0);
            float2 x1 = *(const float2*)(x_ori + i0 + 8 * Nn);
            *(float2*)(out + i0) =
                make_float2(acc[mf][nf][0] + b0v + x0.x, acc[mf][nf][1] + b0v + x0.y);
            *(float2*)(out + i0 + 8 * Nn) =
                make_float2(acc[mf][nf][2] + b1v + x1.x, acc[mf][nf][3] + b1v + x1.y);
        }
    }
}

// ============================================================================
// Launch
// ============================================================================
extern "C" void kernel_launch(void* const* d_in, const int* in_sizes, int n_in,
                              void* d_out, int out_size)
{
    (void)in_sizes; (void)n_in; (void)out_size;
    const float* x_ori  = (const float*)d_in[0];
    const float* cross  = (const float*)d_in[1];
    const float* W_proj = (const float*)d_in[2];
    const float* b_proj = (const float*)d_in[3];
    const float* W_dep  = (const float*)d_in[4];
    const float* b_dep  = (const float*)d_in[5];
    float* out = (float*)d_out;

    k_proj_mma<<<dim3(32, 6), 256>>>(W_proj, cross, b_proj);
    k_mpart<<<dim3(Hh, Bb), 256>>>(cross);
    k_mred<<<128, 256>>>();
    k_out<<<dim3(Bb * Hh, 4), 128>>>(x_ori);
    k_deproj_mma<<<dim3(32, 6), 256>>>(W_dep, b_dep, x_ori, out);
}

// round 14
// speedup vs baseline: 1.3440x; 1.0146x over previous
#include <cuda_runtime.h>
#include <cuda_bf16.h>
#include <cstdint>

// Problem constants
#define Bb   8
#define Cc   768
#define Nn   256
#define Hh   12
#define Dd   64
#define HN   3072          // Hh*Nn
#define CNsz 196608        // Cc*Nn
#define SCALE 0.125f       // D^-0.5
#define GNT  24            // K tiles of 32 (K = 768)

// Scratch (allocation-free: __device__ globals)
__device__ __align__(16) float g_cp[Bb * CNsz];                // proj out [B,C,N]
__device__ __align__(16) float g_Mpart[Bb * Hh * Dd * Dd];     // per-(b,h) 64x64
__device__ __align__(16) __nv_bfloat16 g_Mth[Bb * Dd * Dd];    // M^T hi [b][d'][d], pre-scaled
__device__ __align__(16) __nv_bfloat16 g_Mtl[Bb * Dd * Dd];    // M^T lo
__device__ __align__(16) __nv_bfloat16 g_Uhi[Bb * Nn * Cc];    // U hi [B,N,C]
__device__ __align__(16) __nv_bfloat16 g_Ulo[Bb * Nn * Cc];    // U lo [B,N,C]

// ---- packed f32x2 helpers (for k_mpart) ----
#define FMA_F32X2(d, a, b, c) \
    asm("fma.rn.f32x2 %0, %1, %2, %3;" : "=l"(d) : "l"(a), "l"(b), "l"(c))

static __device__ __forceinline__ unsigned long long splat2(float x) {
    unsigned long long r;
    unsigned u = __float_as_uint(x);
    asm("mov.b64 %0, {%1, %1};" : "=l"(r) : "r"(u));
    return r;
}
static __device__ __forceinline__ float2 unpack2(unsigned long long v) {
    unsigned lo, hi;
    asm("mov.b64 {%0, %1}, %2;" : "=r"(lo), "=r"(hi) : "l"(v));
    return make_float2(__uint_as_float(lo), __uint_as_float(hi));
}

// ---- tensor-core primitives ----
static __device__ __forceinline__ uint32_t smem_u32(const void* p) {
    return (uint32_t)__cvta_generic_to_shared(p);
}

#define LDSM_X4(r0, r1, r2, r3, addr) \
    asm volatile("ldmatrix.sync.aligned.m8n8.x4.shared.b16 {%0,%1,%2,%3}, [%4];" \
        : "=r"(r0), "=r"(r1), "=r"(r2), "=r"(r3) : "r"(addr))

#define LDSM_X4_T(r0, r1, r2, r3, addr) \
    asm volatile("ldmatrix.sync.aligned.m8n8.x4.trans.shared.b16 {%0,%1,%2,%3}, [%4];" \
        : "=r"(r0), "=r"(r1), "=r"(r2), "=r"(r3) : "r"(addr))

#define MMA_BF16(D, a0, a1, a2, a3, b0, b1) \
    asm volatile("mma.sync.aligned.m16n8k16.row.col.f32.bf16.bf16.f32 " \
        "{%0,%1,%2,%3}, {%4,%5,%6,%7}, {%8,%9}, {%0,%1,%2,%3};" \
        : "+f"((D)[0]), "+f"((D)[1]), "+f"((D)[2]), "+f"((D)[3]) \
        : "r"(a0), "r"(a1), "r"(a2), "r"(a3), "r"(b0), "r"(b1))

// Split 8 fp32 -> bf16 hi chunk (16B) + bf16 lo chunk (16B)
static __device__ __forceinline__ void split8(float4 u, float4 v, uint4& hi, uint4& lo) {
    float f[8] = {u.x, u.y, u.z, u.w, v.x, v.y, v.z, v.w};
    uint32_t hw[4], lw[4];
#pragma unroll
    for (int i = 0; i < 4; i++) {
        __nv_bfloat16 h0 = __float2bfloat16(f[2 * i]);
        __nv_bfloat16 h1 = __float2bfloat16(f[2 * i + 1]);
        __nv_bfloat16 l0 = __float2bfloat16(f[2 * i] - __bfloat162float(h0));
        __nv_bfloat16 l1 = __float2bfloat16(f[2 * i + 1] - __bfloat162float(h1));
        __nv_bfloat162 hh(h0, h1), ll(l0, l1);
        hw[i] = *reinterpret_cast<uint32_t*>(&hh);
        lw[i] = *reinterpret_cast<uint32_t*>(&ll);
    }
    hi = make_uint4(hw[0], hw[1], hw[2], hw[3]);
    lo = make_uint4(lw[0], lw[1], lw[2], lw[3]);
}

// ============================================================================
// Kernel 1: cp = W_proj @ cross + b_proj, bf16 3-split tensor core.
// (101.1us winner, verbatim.)
// ============================================================================
__global__ __launch_bounds__(256, 2) void k_proj_mma(
    const float* __restrict__ W, const float* __restrict__ cross,
    const float* __restrict__ bias)
{
    __shared__ uint4 As4[2][128][8];
    __shared__ uint4 Bs4[2][64][8];
    const int tid = threadIdx.x;
    const int wid = tid >> 5, lane = tid & 31;
    const int b = blockIdx.x >> 2;
    const int noff = (blockIdx.x & 3) * 64;
    const int otile = blockIdx.y * 128;

    const int wm = (wid >> 1) * 32;
    const int wn = (wid & 1) * 32;
    const int l7 = lane & 7, l15 = lane & 15, lsel = lane >> 4;
    const int g = lane >> 2, tc = lane & 3;

    const int arow = tid >> 2, akseg = tid & 3;
    const int am7 = arow & 7;
    const int bkrow = tid >> 3, bnseg = tid & 7;
    const int bk7 = bkrow & 7;

    const float* Agp = W + (size_t)(otile + arow) * Cc + akseg * 8;
    const float* Bgp = cross + (size_t)b * CNsz + (size_t)bkrow * Nn + noff + bnseg * 8;

    const uint32_t as_base = smem_u32(&As4[0][0][0]);
    const uint32_t bs_base = smem_u32(&Bs4[0][0][0]);

    float acc[2][4][4];
#pragma unroll
    for (int i = 0; i < 2; i++)
#pragma unroll
        for (int j = 0; j < 4; j++)
#pragma unroll
            for (int e = 0; e < 4; e++) acc[i][j][e] = 0.f;

    float4 a0[2], a1[2], bv[2];
    a0[0] = *(const float4*)(Agp);
    a0[1] = *(const float4*)(Agp + 4);
    a1[0] = *(const float4*)(Agp + (size_t)64 * Cc);
    a1[1] = *(const float4*)(Agp + (size_t)64 * Cc + 4);
    bv[0] = *(const float4*)(Bgp);
    bv[1] = *(const float4*)(Bgp + 4);

    {
        uint4 h, l;
        split8(a0[0], a0[1], h, l);
        As4[0][arow][akseg ^ am7] = h;
        As4[0][arow][(akseg + 4) ^ am7] = l;
        split8(a1[0], a1[1], h, l);
        As4[0][arow + 64][akseg ^ am7] = h;
        As4[0][arow + 64][(akseg + 4) ^ am7] = l;
        split8(bv[0], bv[1], h, l);
        Bs4[0][bkrow][bnseg ^ bk7] = h;
        Bs4[0][bkrow + 32][bnseg ^ bk7] = l;
    }
    __syncthreads();

    for (int kt = 0; kt < GNT; kt++) {
        const int cur = kt & 1;
        if (kt + 1 < GNT) {
            Agp += 32;
            Bgp += (size_t)32 * Nn;
            a0[0] = *(const float4*)(Agp);
            a0[1] = *(const float4*)(Agp + 4);
            a1[0] = *(const float4*)(Agp + (size_t)64 * Cc);
            a1[1] = *(const float4*)(Agp + (size_t)64 * Cc + 4);
            bv[0] = *(const float4*)(Bgp);
            bv[1] = *(const float4*)(Bgp + 4);
        }

        const uint32_t asb = as_base + (uint32_t)cur * 16384;
        const uint32_t bsb = bs_base + (uint32_t)cur * 8192;
#pragma unroll
        for (int ks = 0; ks < 2; ks++) {
            const int k0 = ks * 16;
            uint32_t ah[2][4], al[2][4];
#pragma unroll
            for (int mf = 0; mf < 2; mf++) {
                const uint32_t rbase = asb + (uint32_t)(wm + mf * 16 + l15) * 128;
                const int ch = ((k0 >> 3) + lsel) ^ l7;
                const int cl = ((k0 >> 3) + lsel + 4) ^ l7;
                LDSM_X4(ah[mf][0], ah[mf][1], ah[mf][2], ah[mf][3], rbase + ch * 16);
                LDSM_X4(al[mf][0], al[mf][1], al[mf][2], al[mf][3], rbase + cl * 16);
            }
#pragma unroll
            for (int np = 0; np < 2; np++) {
                const int c = (wn >> 3) + np * 2 + lsel;
                const int p = c ^ l7;
                const uint32_t rb = bsb + (uint32_t)(k0 + l15) * 128 + p * 16;
                uint32_t bh[4], bl[4];
                LDSM_X4_T(bh[0], bh[1], bh[2], bh[3], rb);
                LDSM_X4_T(bl[0], bl[1], bl[2], bl[3], rb + 32 * 128);
#pragma unroll
                for (int mf = 0; mf < 2; mf++) {
                    MMA_BF16(acc[mf][2 * np], ah[mf][0], ah[mf][1], ah[mf][2], ah[mf][3], bh[0], bh[1]);
                    MMA_BF16(acc[mf][2 * np], al[mf][0], al[mf][1], al[mf][2], al[mf][3], bh[0], bh[1]);
                    MMA_BF16(acc[mf][2 * np], ah[mf][0], ah[mf][1], ah[mf][2], ah[mf][3], bl[0], bl[1]);
                    MMA_BF16(acc[mf][2 * np + 1], ah[mf][0], ah[mf][1], ah[mf][2], ah[mf][3], bh[2], bh[3]);
                    MMA_BF16(acc[mf][2 * np + 1], al[mf][0], al[mf][1], al[mf][2], al[mf][3], bh[2], bh[3]);
                    MMA_BF16(acc[mf][2 * np + 1], ah[mf][0], ah[mf][1], ah[mf][2], ah[mf][3], bl[2], bl[3]);
                }
            }
        }

        if (kt + 1 < GNT) {
            const int nxt = cur ^ 1;
            uint4 h, l;
            split8(a0[0], a0[1], h, l);
            As4[nxt][arow][akseg ^ am7] = h;
            As4[nxt][arow][(akseg + 4) ^ am7] = l;
            split8(a1[0], a1[1], h, l);
            As4[nxt][arow + 64][akseg ^ am7] = h;
            As4[nxt][arow + 64][(akseg + 4) ^ am7] = l;
            split8(bv[0], bv[1], h, l);
            Bs4[nxt][bkrow][bnseg ^ bk7] = h;
            Bs4[nxt][bkrow + 32][bnseg ^ bk7] = l;
            __syncthreads();
        }
    }

#pragma unroll
    for (int mf = 0; mf < 2; mf++) {
        const int o = otile + wm + mf * 16 + g;
        const float b0v = bias[o], b1v = bias[o + 8];
        float* base = g_cp + (size_t)b * CNsz + (size_t)o * Nn + noff + wn + tc * 2;
#pragma unroll
        for (int nf = 0; nf < 4; nf++) {
            *(float2*)(base + nf * 8) =
                make_float2(acc[mf][nf][0] + b0v, acc[mf][nf][1] + b0v);
            *(float2*)(base + nf * 8 + 8 * Nn) =
                make_float2(acc[mf][nf][2] + b1v, acc[mf][nf][3] + b1v);
        }
    }
}

// ============================================================================
// Kernel 2: Mpart[b,h][d,d'] = sum_n cp[b,d*H+h,n] * cross[b,d'*H+h,n]
// (101.1us winner, verbatim.)
// ============================================================================
__global__ __launch_bounds__(256) void k_mpart(const float* __restrict__ cross)
{
    __shared__ float As[16][64];
    __shared__ float Bs[16][64];
    const int h = blockIdx.x;
    const int b = blockIdx.y;
    const int tid = threadIdx.x;
    const int r = tid >> 4, c = tid & 15;
    const int lr = tid >> 2, lk = (tid & 3) * 4;

    const float* Ab = g_cp + (size_t)b * CNsz + h * Nn;
    const float* Bp = cross + (size_t)b * CNsz + h * Nn;

    unsigned long long acc[4][2];
#pragma unroll
    for (int i = 0; i < 4; i++) { acc[i][0] = 0ull; acc[i][1] = 0ull; }

    for (int k0 = 0; k0 < Nn; k0 += 16) {
        float4 av = *(const float4*)(Ab + (size_t)lr * HN + k0 + lk);
        float4 bv = *(const float4*)(Bp + (size_t)lr * HN + k0 + lk);
        __syncthreads();
        As[lk + 0][lr] = av.x; As[lk + 1][lr] = av.y;
        As[lk + 2][lr] = av.z; As[lk + 3][lr] = av.w;
        Bs[lk + 0][lr] = bv.x; Bs[lk + 1][lr] = bv.y;
        Bs[lk + 2][lr] = bv.z; Bs[lk + 3][lr] = bv.w;
        __syncthreads();
#pragma unroll
        for (int k = 0; k < 16; k++) {
            float4 ar = *(const float4*)&As[k][r * 4];
            ulonglong2 bp = *(const ulonglong2*)&Bs[k][c * 4];
            unsigned long long sv;
            sv = splat2(ar.x);
            FMA_F32X2(acc[0][0], sv, bp.x, acc[0][0]);
            FMA_F32X2(acc[0][1], sv, bp.y, acc[0][1]);
            sv = splat2(ar.y);
            FMA_F32X2(acc[1][0], sv, bp.x, acc[1][0]);
            FMA_F32X2(acc[1][1], sv, bp.y, acc[1][1]);
            sv = splat2(ar.z);
            FMA_F32X2(acc[2][0], sv, bp.x, acc[2][0]);
            FMA_F32X2(acc[2][1], sv, bp.y, acc[2][1]);
            sv = splat2(ar.w);
            FMA_F32X2(acc[3][0], sv, bp.x, acc[3][0]);
            FMA_F32X2(acc[3][1], sv, bp.y, acc[3][1]);
        }
    }

    float* mp = g_Mpart + ((size_t)b * Hh + h) * 4096;
#pragma unroll
    for (int i = 0; i < 4; i++) {
        float2 lo = unpack2(acc[i][0]);
        float2 hi = unpack2(acc[i][1]);
        *(float4*)(mp + (size_t)(r * 4 + i) * 64 + c * 4) =
            make_float4(lo.x, lo.y, hi.x, hi.y);
    }
}

// ============================================================================
// Kernel 2b: Mt planes = split(SCALE * sum_h Mpart[b,h])^T, [b][d'][d] bf16.
// ============================================================================
__global__ __launch_bounds__(256) void k_mred_t()
{
    const int idx = blockIdx.x * 256 + threadIdx.x;   // 32768
    const int b = idx >> 12;
    const int e = idx & 4095;        // e = d*64 + d'
    const int d = e >> 6, dp = e & 63;
    float s = 0.f;
#pragma unroll
    for (int h = 0; h < Hh; h++)
        s += g_Mpart[((size_t)b * Hh + h) * 4096 + e];
    s *= SCALE;
    __nv_bfloat16 hv = __float2bfloat16(s);
    __nv_bfloat16 lv = __float2bfloat16(s - __bfloat162float(hv));
    g_Mth[(size_t)b * 4096 + dp * 64 + d] = hv;
    g_Mtl[(size_t)b * 4096 + dp * 64 + d] = lv;
}

// ============================================================================
// Kernel 3: k_out_mma — U[m, d'] = sum_d X[d,m] * M[d,d'] on tensor cores.
// Block = (b, h, m-half): A = X^T tile 128(m) x 64(k), staged [k][m] (trans
// LDSM, contiguous loads); B = M^T planes [d'][d]. K=64 single staging,
// bf16 3-split, fp32 accum. Grid (96, 2) = 192 blocks, 256 threads.
// ============================================================================
__global__ __launch_bounds__(256) void k_out_mma(const float* __restrict__ x_ori)
{
    __shared__ uint4 As4[128][16];   // rows 0-63: k=d hi plane; 64-127: lo. 16 chunks = 128 m
    __shared__ uint4 BsH[64][8];     // [d'][d-chunks] hi, swizzled
    __shared__ uint4 BsL[64][8];     // lo
    const int tid = threadIdx.x;
    const int wid = tid >> 5, lane = tid & 31;
    const int b = blockIdx.x / Hh;
    const int h = blockIdx.x % Hh;
    const int mhalf = blockIdx.y;    // 0 or 1: m-range h*256 + mhalf*128 ..

    const int wm = (wid >> 1) * 32;  // 0,32,64,96
    const int wn = (wid & 1) * 32;   // 0,32
    const int l7 = lane & 7, l15 = lane & 15, lsel = lane >> 4;
    const int ksel = (lane >> 3) & 1;
    const int rowNl = (lane & 7) + (lsel << 3);
    const int g = lane >> 2, tc = lane & 3;

    // --- stage A: [k=d rows][m cols], split hi/lo ---
    {
        const int d = tid >> 2;            // 0..63
        const int mseg = (tid & 3) * 32;   // 0,32,64,96
        const int d7 = d & 7;
        const float* xr = x_ori + (size_t)b * CNsz + (size_t)(d * Hh + h) * Nn
                          + mhalf * 128 + mseg;
        float4 v[8];
#pragma unroll
        for (int j = 0; j < 8; j++) v[j] = ((const float4*)xr)[j];
#pragma unroll
        for (int j = 0; j < 4; j++) {
            uint4 hi, lo;
            split8(v[2 * j], v[2 * j + 1], hi, lo);
            const int c = (mseg >> 3) + j;              // 0..15
            const int p = (c & 8) | ((c ^ d7) & 7);
            As4[d][p] = hi;
            As4[d + 64][p] = lo;
        }
    }
    // --- stage B: M^T planes [d'][d], swizzled ---
    {
#pragma unroll
        for (int r = 0; r < 2; r++) {
            const int i = tid + r * 256;   // 0..511
            const int dp = i >> 3, c = i & 7;
            const int p = c ^ (dp & 7);
            BsH[dp][p] = ((const uint4*)(g_Mth + (size_t)b * 4096))[i];
            BsL[dp][p] = ((const uint4*)(g_Mtl + (size_t)b * 4096))[i];
        }
    }
    __syncthreads();

    const uint32_t asb = smem_u32(&As4[0][0]);
    const uint32_t bhb = smem_u32(&BsH[0][0]);
    const uint32_t blb = smem_u32(&BsL[0][0]);

    float acc[2][4][4];
#pragma unroll
    for (int i = 0; i < 2; i++)
#pragma unroll
        for (int j = 0; j < 4; j++)
#pragma unroll
            for (int e = 0; e < 4; e++) acc[i][j][e] = 0.f;

#pragma unroll
    for (int ks = 0; ks < 4; ks++) {
        uint32_t ah[2][4], al[2][4];
#pragma unroll
        for (int mf = 0; mf < 2; mf++) {
            const int c = ((wm + mf * 16) >> 3) + lsel;
            const int p = (c & 8) | ((c ^ l7) & 7);
            const uint32_t rowk = (uint32_t)(ks * 16 + l15);
            uint32_t t0, t1, t2, t3;
            LDSM_X4_T(t0, t1, t2, t3, asb + rowk * 256 + p * 16);
            ah[mf][0] = t0; ah[mf][1] = t2; ah[mf][2] = t1; ah[mf][3] = t3;
            LDSM_X4_T(t0, t1, t2, t3, asb + (rowk + 64) * 256 + p * 16);
            al[mf][0] = t0; al[mf][1] = t2; al[mf][2] = t1; al[mf][3] = t3;
        }
#pragma unroll
        for (int np = 0; np < 2; np++) {
            const int rowN = wn + np * 16 + rowNl;
            const int ch = (ks * 2 + ksel) ^ l7;
            uint32_t bh[4], bl[4];
            LDSM_X4(bh[0], bh[1], bh[2], bh[3], bhb + (uint32_t)rowN * 128 + ch * 16);
            LDSM_X4(bl[0], bl[1], bl[2], bl[3], blb + (uint32_t)rowN * 128 + ch * 16);
#pragma unroll
            for (int mf = 0; mf < 2; mf++) {
                MMA_BF16(acc[mf][2 * np], ah[mf][0], ah[mf][1], ah[mf][2], ah[mf][3], bh[0], bh[1]);
                MMA_BF16(acc[mf][2 * np], al[mf][0], al[mf][1], al[mf][2], al[mf][3], bh[0], bh[1]);
                MMA_BF16(acc[mf][2 * np], ah[mf][0], ah[mf][1], ah[mf][2], ah[mf][3], bl[0], bl[1]);
                MMA_BF16(acc[mf][2 * np + 1], ah[mf][0], ah[mf][1], ah[mf][2], ah[mf][3], bh[2], bh[3]);
                MMA_BF16(acc[mf][2 * np + 1], al[mf][0], al[mf][1], al[mf][2], al[mf][3], bh[2], bh[3]);
                MMA_BF16(acc[mf][2 * np + 1], ah[mf][0], ah[mf][1], ah[mf][2], ah[mf][3], bl[2], bl[3]);
            }
        }
    }

    // Epilogue: split to U planes, permuted (nf, hf) write
    const int mbase = h * 256 + mhalf * 128;
#pragma unroll
    for (int mf = 0; mf < 2; mf++) {
#pragma unroll
        for (int rh = 0; rh < 2; rh++) {
            const int m = mbase + wm + mf * 16 + g + rh * 8;
            const int nf = m / Hh;
            const int hf = m - nf * Hh;
            const size_t rowoff = ((size_t)b * Nn + nf) * Cc + hf * Dd + wn + tc * 2;
#pragma unroll
            for (int j = 0; j < 4; j++) {
                const float e0 = acc[mf][j][2 * rh];
                const float e1 = acc[mf][j][2 * rh + 1];
                __nv_bfloat16 h0 = __float2bfloat16(e0);
                __nv_bfloat16 h1 = __float2bfloat16(e1);
                __nv_bfloat16 l0 = __float2bfloat16(e0 - __bfloat162float(h0));
                __nv_bfloat16 l1 = __float2bfloat16(e1 - __bfloat162float(h1));
                __nv_bfloat162 hh(h0, h1), ll(l0, l1);
                *(uint32_t*)(g_Uhi + rowoff + j * 8) = *reinterpret_cast<uint32_t*>(&hh);
                *(uint32_t*)(g_Ulo + rowoff + j * 8) = *reinterpret_cast<uint32_t*>(&ll);
            }
        }
    }
}

// ============================================================================
// Kernel 4: out = x_ori + b_dep + U @ W_dep^T, bf16 3-split tensor core.
// (101.1us winner, verbatim.)
// ============================================================================
__global__ __launch_bounds__(256, 2) void k_deproj_mma(
    const float* __restrict__ Wdep, const float* __restrict__ bdep,
    const float* __restrict__ x_ori, float* __restrict__ out)
{
    __shared__ uint4 As4[2][128][8];
    __shared__ uint4 Bs4[2][64][8];
    const int tid = threadIdx.x;
    const int wid = tid >> 5, lane = tid & 31;
    const int b = blockIdx.x >> 2;
    const int noff = (blockIdx.x & 3) * 64;
    const int otile = blockIdx.y * 128;

    const int wm = (wid >> 1) * 32;
    const int wn = (wid & 1) * 32;
    const int l7 = lane & 7, l15 = lane & 15, lsel = lane >> 4;
    const int ksel = (lane >> 3) & 1;
    const int rowNl = (lane & 7) + (lsel << 3);
    const int g = lane >> 2, tc = lane & 3;

    const int arow = tid >> 2, akseg = tid & 3;
    const int am7 = arow & 7;
    const int bnrow = tid >> 3, bc = tid & 7;
    const int bn7 = bnrow & 7;

    const float* Agp = Wdep + (size_t)(otile + arow) * Cc + akseg * 8;
    const __nv_bfloat16* Usrc = (bc < 4) ? g_Uhi : g_Ulo;
    const __nv_bfloat16* Ugp =
        Usrc + ((size_t)b * Nn + noff + bnrow) * Cc + (bc & 3) * 8;

    const uint32_t as_base = smem_u32(&As4[0][0][0]);
    const uint32_t bs_base = smem_u32(&Bs4[0][0][0]);

    float acc[2][4][4];
#pragma unroll
    for (int i = 0; i < 2; i++)
#pragma unroll
        for (int j = 0; j < 4; j++)
#pragma unroll
            for (int e = 0; e < 4; e++) acc[i][j][e] = 0.f;

    float4 a0[2], a1[2];
    uint4 u0, u1;
    a0[0] = *(const float4*)(Agp);
    a0[1] = *(const float4*)(Agp + 4);
    a1[0] = *(const float4*)(Agp + (size_t)64 * Cc);
    a1[1] = *(const float4*)(Agp + (size_t)64 * Cc + 4);
    u0 = *(const uint4*)(Ugp);
    u1 = *(const uint4*)(Ugp + (size_t)32 * Cc);

    {
        uint4 h, l;
        split8(a0[0], a0[1], h, l);
        As4[0][arow][akseg ^ am7] = h;
        As4[0][arow][(akseg + 4) ^ am7] = l;
        split8(a1[0], a1[1], h, l);
        As4[0][arow + 64][akseg ^ am7] = h;
        As4[0][arow + 64][(akseg + 4) ^ am7] = l;
        Bs4[0][bnrow][bc ^ bn7] = u0;
        Bs4[0][bnrow + 32][bc ^ bn7] = u1;
    }
    __syncthreads();

    for (int kt = 0; kt < GNT; kt++) {
        const int cur = kt & 1;
        if (kt + 1 < GNT) {
            Agp += 32;
            Ugp += 32;
            a0[0] = *(const float4*)(Agp);
            a0[1] = *(const float4*)(Agp + 4);
            a1[0] = *(const float4*)(Agp + (size_t)64 * Cc);
            a1[1] = *(const float4*)(Agp + (size_t)64 * Cc + 4);
            u0 = *(const uint4*)(Ugp);
            u1 = *(const uint4*)(Ugp + (size_t)32 * Cc);
        }

        const uint32_t asb = as_base + (uint32_t)cur * 16384;
        const uint32_t bsb = bs_base + (uint32_t)cur * 8192;
#pragma unroll
        for (int ks = 0; ks < 2; ks++) {
            const int k0 = ks * 16;
            uint32_t ah[2][4], al[2][4];
#pragma unroll
            for (int mf = 0; mf < 2; mf++) {
                const uint32_t rbase = asb + (uint32_t)(wm + mf * 16 + l15) * 128;
                const int ch = ((k0 >> 3) + lsel) ^ l7;
                const int cl = ((k0 >> 3) + lsel + 4) ^ l7;
                LDSM_X4(ah[mf][0], ah[mf][1], ah[mf][2], ah[mf][3], rbase + ch * 16);
                LDSM_X4(al[mf][0], al[mf][1], al[mf][2], al[mf][3], rbase + cl * 16);
            }
#pragma unroll
            for (int np = 0; np < 2; np++) {
                const int rowN = wn + np * 16 + rowNl;
                const int ch = ((k0 >> 3) + ksel) ^ l7;
                const int cl = ((k0 >> 3) + ksel + 4) ^ l7;
                const uint32_t rb = bsb + (uint32_t)rowN * 128;
                uint32_t bh[4], bl[4];
                LDSM_X4(bh[0], bh[1], bh[2], bh[3], rb + ch * 16);
                LDSM_X4(bl[0], bl[1], bl[2], bl[3], rb + cl * 16);
#pragma unroll
                for (int mf = 0; mf < 2; mf++) {
                    MMA_BF16(acc[mf][2 * np], ah[mf][0], ah[mf][1], ah[mf][2], ah[mf][3], bh[0], bh[1]);
                    MMA_BF16(acc[mf][2 * np], al[mf][0], al[mf][1], al[mf][2], al[mf][3], bh[0], bh[1]);
                    MMA_BF16(acc[mf][2 * np], ah[mf][0], ah[mf][1], ah[mf][2], ah[mf][3], bl[0], bl[1]);
                    MMA_BF16(acc[mf][2 * np + 1], ah[mf][0], ah[mf][1], ah[mf][2], ah[mf][3], bh[2], bh[3]);
                    MMA_BF16(acc[mf][2 * np + 1], al[mf][0], al[mf][1], al[mf][2], al[mf][3], bh[2], bh[3]);
                    MMA_BF16(acc[mf][2 * np + 1], ah[mf][0], ah[mf][1], ah[mf][2], ah[mf][3], bl[2], bl[3]);
                }
            }
        }

        if (kt + 1 < GNT) {
            const int nxt = cur ^ 1;
            uint4 h, l;
            split8(a0[0], a0[1], h, l);
            As4[nxt][arow][akseg ^ am7] = h;
            As4[nxt][arow][(akseg + 4) ^ am7] = l;
            split8(a1[0], a1[1], h, l);
            As4[nxt][arow + 64][akseg ^ am7] = h;
            As4[nxt][arow + 64][(akseg + 4) ^ am7] = l;
            Bs4[nxt][bnrow][bc ^ bn7] = u0;
            Bs4[nxt][bnrow + 32][bc ^ bn7] = u1;
            __syncthreads();
        }
    }

#pragma unroll
    for (int mf = 0; mf < 2; mf++) {
        const int o = otile + wm + mf * 16 + g;
        const float b0v = bdep[o], b1v = bdep[o + 8];
        const size_t base = (size_t)b * CNsz + (size_t)o * Nn + noff + wn + tc * 2;
#pragma unroll
        for (int nf = 0; nf < 4; nf++) {
            const size_t i0 = base + nf * 8;
            float2 x0 = *(const float2*)(x_ori + i0);
            float2 x1 = *(const float2*)(x_ori + i0 + 8 * Nn);
            *(float2*)(out + i0) =
                make_float2(acc[mf][nf][0] + b0v + x0.x, acc[mf][nf][1] + b0v + x0.y);
            *(float2*)(out + i0 + 8 * Nn) =
                make_float2(acc[mf][nf][2] + b1v + x1.x, acc[mf][nf][3] + b1v + x1.y);
        }
    }
}

// ============================================================================
// Launch
// ============================================================================
extern "C" void kernel_launch(void* const* d_in, const int* in_sizes, int n_in,
                              void* d_out, int out_size)
{
    (void)in_sizes; (void)n_in; (void)out_size;
    const float* x_ori  = (const float*)d_in[0];
    const float* cross  = (const float*)d_in[1];
    const float* W_proj = (const float*)d_in[2];
    const float* b_proj = (const float*)d_in[3];
    const float* W_dep  = (const float*)d_in[4];
    const float* b_dep  = (const float*)d_in[5];
    float* out = (float*)d_out;

    k_proj_mma<<<dim3(32, 6), 256>>>(W_proj, cross, b_proj);
    k_mpart<<<dim3(Hh, Bb), 256>>>(cross);
    k_mred_t<<<128, 256>>>();
    k_out_mma<<<dim3(Bb * Hh, 2), 256>>>(x_ori);
    k_deproj_mma<<<dim3(32, 6), 256>>>(W_dep, b_dep, x_ori, out);
}

// round 15
// speedup vs baseline: 1.3478x; 1.0029x over previous
#include <cuda_runtime.h>
#include <cuda_bf16.h>
#include <cstdint>

// Problem constants
#define Bb   8
#define Cc   768
#define Nn   256
#define Hh   12
#define Dd   64
#define HN   3072          // Hh*Nn
#define CNsz 196608        // Cc*Nn
#define SCALE 0.125f       // D^-0.5
#define GNT  24            // K tiles of 32 (K = 768)

// Scratch (allocation-free: __device__ globals)
__device__ __align__(16) float g_cp[Bb * CNsz];                // proj out [B,C,N]
__device__ __align__(16) float g_Mpart[Bb * Hh * Dd * Dd];     // per-(b,h) 64x64
__device__ __align__(16) __nv_bfloat16 g_Mth[Bb * Dd * Dd];    // M^T hi [b][d'][d], pre-scaled
__device__ __align__(16) __nv_bfloat16 g_Mtl[Bb * Dd * Dd];    // M^T lo
__device__ __align__(16) __nv_bfloat16 g_Uhi[Bb * Nn * Cc];    // U hi [B,N,C]
__device__ __align__(16) __nv_bfloat16 g_Ulo[Bb * Nn * Cc];    // U lo [B,N,C]

// ---- packed f32x2 helpers (for k_mpart) ----
#define FMA_F32X2(d, a, b, c) \
    asm("fma.rn.f32x2 %0, %1, %2, %3;" : "=l"(d) : "l"(a), "l"(b), "l"(c))

static __device__ __forceinline__ unsigned long long splat2(float x) {
    unsigned long long r;
    unsigned u = __float_as_uint(x);
    asm("mov.b64 %0, {%1, %1};" : "=l"(r) : "r"(u));
    return r;
}
static __device__ __forceinline__ float2 unpack2(unsigned long long v) {
    unsigned lo, hi;
    asm("mov.b64 {%0, %1}, %2;" : "=r"(lo), "=r"(hi) : "l"(v));
    return make_float2(__uint_as_float(lo), __uint_as_float(hi));
}

// ---- tensor-core primitives ----
static __device__ __forceinline__ uint32_t smem_u32(const void* p) {
    return (uint32_t)__cvta_generic_to_shared(p);
}

#define LDSM_X4(r0, r1, r2, r3, addr) \
    asm volatile("ldmatrix.sync.aligned.m8n8.x4.shared.b16 {%0,%1,%2,%3}, [%4];" \
        : "=r"(r0), "=r"(r1), "=r"(r2), "=r"(r3) : "r"(addr))

#define LDSM_X4_T(r0, r1, r2, r3, addr) \
    asm volatile("ldmatrix.sync.aligned.m8n8.x4.trans.shared.b16 {%0,%1,%2,%3}, [%4];" \
        : "=r"(r0), "=r"(r1), "=r"(r2), "=r"(r3) : "r"(addr))

#define MMA_BF16(D, a0, a1, a2, a3, b0, b1) \
    asm volatile("mma.sync.aligned.m16n8k16.row.col.f32.bf16.bf16.f32 " \
        "{%0,%1,%2,%3}, {%4,%5,%6,%7}, {%8,%9}, {%0,%1,%2,%3};" \
        : "+f"((D)[0]), "+f"((D)[1]), "+f"((D)[2]), "+f"((D)[3]) \
        : "r"(a0), "r"(a1), "r"(a2), "r"(a3), "r"(b0), "r"(b1))

// Split 8 fp32 -> bf16 hi chunk (16B) + bf16 lo chunk (16B)
static __device__ __forceinline__ void split8(float4 u, float4 v, uint4& hi, uint4& lo) {
    float f[8] = {u.x, u.y, u.z, u.w, v.x, v.y, v.z, v.w};
    uint32_t hw[4], lw[4];
#pragma unroll
    for (int i = 0; i < 4; i++) {
        __nv_bfloat16 h0 = __float2bfloat16(f[2 * i]);
        __nv_bfloat16 h1 = __float2bfloat16(f[2 * i + 1]);
        __nv_bfloat16 l0 = __float2bfloat16(f[2 * i] - __bfloat162float(h0));
        __nv_bfloat16 l1 = __float2bfloat16(f[2 * i + 1] - __bfloat162float(h1));
        __nv_bfloat162 hh(h0, h1), ll(l0, l1);
        hw[i] = *reinterpret_cast<uint32_t*>(&hh);
        lw[i] = *reinterpret_cast<uint32_t*>(&ll);
    }
    hi = make_uint4(hw[0], hw[1], hw[2], hw[3]);
    lo = make_uint4(lw[0], lw[1], lw[2], lw[3]);
}

// Three-pass MMA emission: all hh (8 independent), then lh, then hl.
#define EMIT_MMAS_3PASS(acc_, ah_, al_, bh_, bl_)                             \
    _Pragma("unroll")                                                         \
    for (int np = 0; np < 2; np++)                                            \
        _Pragma("unroll")                                                     \
        for (int mf = 0; mf < 2; mf++) {                                      \
            MMA_BF16(acc_[mf][2 * np], ah_[mf][0], ah_[mf][1], ah_[mf][2], ah_[mf][3], bh_[np][0], bh_[np][1]); \
            MMA_BF16(acc_[mf][2 * np + 1], ah_[mf][0], ah_[mf][1], ah_[mf][2], ah_[mf][3], bh_[np][2], bh_[np][3]); \
        }                                                                     \
    _Pragma("unroll")                                                         \
    for (int np = 0; np < 2; np++)                                            \
        _Pragma("unroll")                                                     \
        for (int mf = 0; mf < 2; mf++) {                                      \
            MMA_BF16(acc_[mf][2 * np], al_[mf][0], al_[mf][1], al_[mf][2], al_[mf][3], bh_[np][0], bh_[np][1]); \
            MMA_BF16(acc_[mf][2 * np + 1], al_[mf][0], al_[mf][1], al_[mf][2], al_[mf][3], bh_[np][2], bh_[np][3]); \
        }                                                                     \
    _Pragma("unroll")                                                         \
    for (int np = 0; np < 2; np++)                                            \
        _Pragma("unroll")                                                     \
        for (int mf = 0; mf < 2; mf++) {                                      \
            MMA_BF16(acc_[mf][2 * np], ah_[mf][0], ah_[mf][1], ah_[mf][2], ah_[mf][3], bl_[np][0], bl_[np][1]); \
            MMA_BF16(acc_[mf][2 * np + 1], ah_[mf][0], ah_[mf][1], ah_[mf][2], ah_[mf][3], bl_[np][2], bl_[np][3]); \
        }

// ============================================================================
// Kernel 1: cp = W_proj @ cross + b_proj, bf16 3-split tensor core.
// 128x64 double-buffered skeleton; MMAs reordered into 3 independent passes.
// ============================================================================
__global__ __launch_bounds__(256, 2) void k_proj_mma(
    const float* __restrict__ W, const float* __restrict__ cross,
    const float* __restrict__ bias)
{
    __shared__ uint4 As4[2][128][8];
    __shared__ uint4 Bs4[2][64][8];
    const int tid = threadIdx.x;
    const int wid = tid >> 5, lane = tid & 31;
    const int b = blockIdx.x >> 2;
    const int noff = (blockIdx.x & 3) * 64;
    const int otile = blockIdx.y * 128;

    const int wm = (wid >> 1) * 32;
    const int wn = (wid & 1) * 32;
    const int l7 = lane & 7, l15 = lane & 15, lsel = lane >> 4;
    const int g = lane >> 2, tc = lane & 3;

    const int arow = tid >> 2, akseg = tid & 3;
    const int am7 = arow & 7;
    const int bkrow = tid >> 3, bnseg = tid & 7;
    const int bk7 = bkrow & 7;

    const float* Agp = W + (size_t)(otile + arow) * Cc + akseg * 8;
    const float* Bgp = cross + (size_t)b * CNsz + (size_t)bkrow * Nn + noff + bnseg * 8;

    const uint32_t as_base = smem_u32(&As4[0][0][0]);
    const uint32_t bs_base = smem_u32(&Bs4[0][0][0]);

    float acc[2][4][4];
#pragma unroll
    for (int i = 0; i < 2; i++)
#pragma unroll
        for (int j = 0; j < 4; j++)
#pragma unroll
            for (int e = 0; e < 4; e++) acc[i][j][e] = 0.f;

    float4 a0[2], a1[2], bv[2];
    a0[0] = *(const float4*)(Agp);
    a0[1] = *(const float4*)(Agp + 4);
    a1[0] = *(const float4*)(Agp + (size_t)64 * Cc);
    a1[1] = *(const float4*)(Agp + (size_t)64 * Cc + 4);
    bv[0] = *(const float4*)(Bgp);
    bv[1] = *(const float4*)(Bgp + 4);

    {
        uint4 h, l;
        split8(a0[0], a0[1], h, l);
        As4[0][arow][akseg ^ am7] = h;
        As4[0][arow][(akseg + 4) ^ am7] = l;
        split8(a1[0], a1[1], h, l);
        As4[0][arow + 64][akseg ^ am7] = h;
        As4[0][arow + 64][(akseg + 4) ^ am7] = l;
        split8(bv[0], bv[1], h, l);
        Bs4[0][bkrow][bnseg ^ bk7] = h;
        Bs4[0][bkrow + 32][bnseg ^ bk7] = l;
    }
    __syncthreads();

    for (int kt = 0; kt < GNT; kt++) {
        const int cur = kt & 1;
        if (kt + 1 < GNT) {
            Agp += 32;
            Bgp += (size_t)32 * Nn;
            a0[0] = *(const float4*)(Agp);
            a0[1] = *(const float4*)(Agp + 4);
            a1[0] = *(const float4*)(Agp + (size_t)64 * Cc);
            a1[1] = *(const float4*)(Agp + (size_t)64 * Cc + 4);
            bv[0] = *(const float4*)(Bgp);
            bv[1] = *(const float4*)(Bgp + 4);
        }

        const uint32_t asb = as_base + (uint32_t)cur * 16384;
        const uint32_t bsb = bs_base + (uint32_t)cur * 8192;
#pragma unroll
        for (int ks = 0; ks < 2; ks++) {
            const int k0 = ks * 16;
            uint32_t ah[2][4], al[2][4], bhv[2][4], blv[2][4];
#pragma unroll
            for (int mf = 0; mf < 2; mf++) {
                const uint32_t rbase = asb + (uint32_t)(wm + mf * 16 + l15) * 128;
                const int ch = ((k0 >> 3) + lsel) ^ l7;
                const int cl = ((k0 >> 3) + lsel + 4) ^ l7;
                LDSM_X4(ah[mf][0], ah[mf][1], ah[mf][2], ah[mf][3], rbase + ch * 16);
                LDSM_X4(al[mf][0], al[mf][1], al[mf][2], al[mf][3], rbase + cl * 16);
            }
#pragma unroll
            for (int np = 0; np < 2; np++) {
                const int c = (wn >> 3) + np * 2 + lsel;
                const int p = c ^ l7;
                const uint32_t rb = bsb + (uint32_t)(k0 + l15) * 128 + p * 16;
                LDSM_X4_T(bhv[np][0], bhv[np][1], bhv[np][2], bhv[np][3], rb);
                LDSM_X4_T(blv[np][0], blv[np][1], blv[np][2], blv[np][3], rb + 32 * 128);
            }
            EMIT_MMAS_3PASS(acc, ah, al, bhv, blv)
        }

        if (kt + 1 < GNT) {
            const int nxt = cur ^ 1;
            uint4 h, l;
            split8(a0[0], a0[1], h, l);
            As4[nxt][arow][akseg ^ am7] = h;
            As4[nxt][arow][(akseg + 4) ^ am7] = l;
            split8(a1[0], a1[1], h, l);
            As4[nxt][arow + 64][akseg ^ am7] = h;
            As4[nxt][arow + 64][(akseg + 4) ^ am7] = l;
            split8(bv[0], bv[1], h, l);
            Bs4[nxt][bkrow][bnseg ^ bk7] = h;
            Bs4[nxt][bkrow + 32][bnseg ^ bk7] = l;
            __syncthreads();
        }
    }

#pragma unroll
    for (int mf = 0; mf < 2; mf++) {
        const int o = otile + wm + mf * 16 + g;
        const float b0v = bias[o], b1v = bias[o + 8];
        float* base = g_cp + (size_t)b * CNsz + (size_t)o * Nn + noff + wn + tc * 2;
#pragma unroll
        for (int nf = 0; nf < 4; nf++) {
            *(float2*)(base + nf * 8) =
                make_float2(acc[mf][nf][0] + b0v, acc[mf][nf][1] + b0v);
            *(float2*)(base + nf * 8 + 8 * Nn) =
                make_float2(acc[mf][nf][2] + b1v, acc[mf][nf][3] + b1v);
        }
    }
}

// ============================================================================
// Kernel 2: Mpart[b,h][d,d'] = sum_n cp[b,d*H+h,n] * cross[b,d'*H+h,n]
// (101.1us winner, verbatim.)
// ============================================================================
__global__ __launch_bounds__(256) void k_mpart(const float* __restrict__ cross)
{
    __shared__ float As[16][64];
    __shared__ float Bs[16][64];
    const int h = blockIdx.x;
    const int b = blockIdx.y;
    const int tid = threadIdx.x;
    const int r = tid >> 4, c = tid & 15;
    const int lr = tid >> 2, lk = (tid & 3) * 4;

    const float* Ab = g_cp + (size_t)b * CNsz + h * Nn;
    const float* Bp = cross + (size_t)b * CNsz + h * Nn;

    unsigned long long acc[4][2];
#pragma unroll
    for (int i = 0; i < 4; i++) { acc[i][0] = 0ull; acc[i][1] = 0ull; }

    for (int k0 = 0; k0 < Nn; k0 += 16) {
        float4 av = *(const float4*)(Ab + (size_t)lr * HN + k0 + lk);
        float4 bv = *(const float4*)(Bp + (size_t)lr * HN + k0 + lk);
        __syncthreads();
        As[lk + 0][lr] = av.x; As[lk + 1][lr] = av.y;
        As[lk + 2][lr] = av.z; As[lk + 3][lr] = av.w;
        Bs[lk + 0][lr] = bv.x; Bs[lk + 1][lr] = bv.y;
        Bs[lk + 2][lr] = bv.z; Bs[lk + 3][lr] = bv.w;
        __syncthreads();
#pragma unroll
        for (int k = 0; k < 16; k++) {
            float4 ar = *(const float4*)&As[k][r * 4];
            ulonglong2 bp = *(const ulonglong2*)&Bs[k][c * 4];
            unsigned long long sv;
            sv = splat2(ar.x);
            FMA_F32X2(acc[0][0], sv, bp.x, acc[0][0]);
            FMA_F32X2(acc[0][1], sv, bp.y, acc[0][1]);
            sv = splat2(ar.y);
            FMA_F32X2(acc[1][0], sv, bp.x, acc[1][0]);
            FMA_F32X2(acc[1][1], sv, bp.y, acc[1][1]);
            sv = splat2(ar.z);
            FMA_F32X2(acc[2][0], sv, bp.x, acc[2][0]);
            FMA_F32X2(acc[2][1], sv, bp.y, acc[2][1]);
            sv = splat2(ar.w);
            FMA_F32X2(acc[3][0], sv, bp.x, acc[3][0]);
            FMA_F32X2(acc[3][1], sv, bp.y, acc[3][1]);
        }
    }

    float* mp = g_Mpart + ((size_t)b * Hh + h) * 4096;
#pragma unroll
    for (int i = 0; i < 4; i++) {
        float2 lo = unpack2(acc[i][0]);
        float2 hi = unpack2(acc[i][1]);
        *(float4*)(mp + (size_t)(r * 4 + i) * 64 + c * 4) =
            make_float4(lo.x, lo.y, hi.x, hi.y);
    }
}

// ============================================================================
// Kernel 2b: Mt planes = split(SCALE * sum_h Mpart[b,h])^T, [b][d'][d] bf16.
// ============================================================================
__global__ __launch_bounds__(256) void k_mred_t()
{
    const int idx = blockIdx.x * 256 + threadIdx.x;   // 32768
    const int b = idx >> 12;
    const int e = idx & 4095;        // e = d*64 + d'
    const int d = e >> 6, dp = e & 63;
    float s = 0.f;
#pragma unroll
    for (int h = 0; h < Hh; h++)
        s += g_Mpart[((size_t)b * Hh + h) * 4096 + e];
    s *= SCALE;
    __nv_bfloat16 hv = __float2bfloat16(s);
    __nv_bfloat16 lv = __float2bfloat16(s - __bfloat162float(hv));
    g_Mth[(size_t)b * 4096 + dp * 64 + d] = hv;
    g_Mtl[(size_t)b * 4096 + dp * 64 + d] = lv;
}

// ============================================================================
// Kernel 3: k_out_mma — U[m, d'] = sum_d X[d,m] * M[d,d'] on tensor cores.
// (R13 structure, MMAs reordered into 3 passes.)
// ============================================================================
__global__ __launch_bounds__(256) void k_out_mma(const float* __restrict__ x_ori)
{
    __shared__ uint4 As4[128][16];
    __shared__ uint4 BsH[64][8];
    __shared__ uint4 BsL[64][8];
    const int tid = threadIdx.x;
    const int wid = tid >> 5, lane = tid & 31;
    const int b = blockIdx.x / Hh;
    const int h = blockIdx.x % Hh;
    const int mhalf = blockIdx.y;

    const int wm = (wid >> 1) * 32;
    const int wn = (wid & 1) * 32;
    const int l7 = lane & 7, l15 = lane & 15, lsel = lane >> 4;
    const int ksel = (lane >> 3) & 1;
    const int rowNl = (lane & 7) + (lsel << 3);
    const int g = lane >> 2, tc = lane & 3;

    {
        const int d = tid >> 2;
        const int mseg = (tid & 3) * 32;
        const int d7 = d & 7;
        const float* xr = x_ori + (size_t)b * CNsz + (size_t)(d * Hh + h) * Nn
                          + mhalf * 128 + mseg;
        float4 v[8];
#pragma unroll
        for (int j = 0; j < 8; j++) v[j] = ((const float4*)xr)[j];
#pragma unroll
        for (int j = 0; j < 4; j++) {
            uint4 hi, lo;
            split8(v[2 * j], v[2 * j + 1], hi, lo);
            const int c = (mseg >> 3) + j;
            const int p = (c & 8) | ((c ^ d7) & 7);
            As4[d][p] = hi;
            As4[d + 64][p] = lo;
        }
    }
    {
#pragma unroll
        for (int r = 0; r < 2; r++) {
            const int i = tid + r * 256;
            const int dp = i >> 3, c = i & 7;
            const int p = c ^ (dp & 7);
            BsH[dp][p] = ((const uint4*)(g_Mth + (size_t)b * 4096))[i];
            BsL[dp][p] = ((const uint4*)(g_Mtl + (size_t)b * 4096))[i];
        }
    }
    __syncthreads();

    const uint32_t asb = smem_u32(&As4[0][0]);
    const uint32_t bhb = smem_u32(&BsH[0][0]);
    const uint32_t blb = smem_u32(&BsL[0][0]);

    float acc[2][4][4];
#pragma unroll
    for (int i = 0; i < 2; i++)
#pragma unroll
        for (int j = 0; j < 4; j++)
#pragma unroll
            for (int e = 0; e < 4; e++) acc[i][j][e] = 0.f;

#pragma unroll
    for (int ks = 0; ks < 4; ks++) {
        uint32_t ah[2][4], al[2][4], bhv[2][4], blv[2][4];
#pragma unroll
        for (int mf = 0; mf < 2; mf++) {
            const int c = ((wm + mf * 16) >> 3) + lsel;
            const int p = (c & 8) | ((c ^ l7) & 7);
            const uint32_t rowk = (uint32_t)(ks * 16 + l15);
            uint32_t t0, t1, t2, t3;
            LDSM_X4_T(t0, t1, t2, t3, asb + rowk * 256 + p * 16);
            ah[mf][0] = t0; ah[mf][1] = t2; ah[mf][2] = t1; ah[mf][3] = t3;
            LDSM_X4_T(t0, t1, t2, t3, asb + (rowk + 64) * 256 + p * 16);
            al[mf][0] = t0; al[mf][1] = t2; al[mf][2] = t1; al[mf][3] = t3;
        }
#pragma unroll
        for (int np = 0; np < 2; np++) {
            const int rowN = wn + np * 16 + rowNl;
            const int ch = (ks * 2 + ksel) ^ l7;
            LDSM_X4(bhv[np][0], bhv[np][1], bhv[np][2], bhv[np][3],
                    bhb + (uint32_t)rowN * 128 + ch * 16);
            LDSM_X4(blv[np][0], blv[np][1], blv[np][2], blv[np][3],
                    blb + (uint32_t)rowN * 128 + ch * 16);
        }
        EMIT_MMAS_3PASS(acc, ah, al, bhv, blv)
    }

    const int mbase = h * 256 + mhalf * 128;
#pragma unroll
    for (int mf = 0; mf < 2; mf++) {
#pragma unroll
        for (int rh = 0; rh < 2; rh++) {
            const int m = mbase + wm + mf * 16 + g + rh * 8;
            const int nf = m / Hh;
            const int hf = m - nf * Hh;
            const size_t rowoff = ((size_t)b * Nn + nf) * Cc + hf * Dd + wn + tc * 2;
#pragma unroll
            for (int j = 0; j < 4; j++) {
                const float e0 = acc[mf][j][2 * rh];
                const float e1 = acc[mf][j][2 * rh + 1];
                __nv_bfloat16 h0 = __float2bfloat16(e0);
                __nv_bfloat16 h1 = __float2bfloat16(e1);
                __nv_bfloat16 l0 = __float2bfloat16(e0 - __bfloat162float(h0));
                __nv_bfloat16 l1 = __float2bfloat16(e1 - __bfloat162float(h1));
                __nv_bfloat162 hh(h0, h1), ll(l0, l1);
                *(uint32_t*)(g_Uhi + rowoff + j * 8) = *reinterpret_cast<uint32_t*>(&hh);
                *(uint32_t*)(g_Ulo + rowoff + j * 8) = *reinterpret_cast<uint32_t*>(&ll);
            }
        }
    }
}

// ============================================================================
// Kernel 4: out = x_ori + b_dep + U @ W_dep^T, bf16 3-split tensor core.
// 128x64 double-buffered skeleton; MMAs reordered into 3 passes.
// ============================================================================
__global__ __launch_bounds__(256, 2) void k_deproj_mma(
    const float* __restrict__ Wdep, const float* __restrict__ bdep,
    const float* __restrict__ x_ori, float* __restrict__ out)
{
    __shared__ uint4 As4[2][128][8];
    __shared__ uint4 Bs4[2][64][8];
    const int tid = threadIdx.x;
    const int wid = tid >> 5, lane = tid & 31;
    const int b = blockIdx.x >> 2;
    const int noff = (blockIdx.x & 3) * 64;
    const int otile = blockIdx.y * 128;

    const int wm = (wid >> 1) * 32;
    const int wn = (wid & 1) * 32;
    const int l7 = lane & 7, l15 = lane & 15, lsel = lane >> 4;
    const int ksel = (lane >> 3) & 1;
    const int rowNl = (lane & 7) + (lsel << 3);
    const int g = lane >> 2, tc = lane & 3;

    const int arow = tid >> 2, akseg = tid & 3;
    const int am7 = arow & 7;
    const int bnrow = tid >> 3, bc = tid & 7;
    const int bn7 = bnrow & 7;

    const float* Agp = Wdep + (size_t)(otile + arow) * Cc + akseg * 8;
    const __nv_bfloat16* Usrc = (bc < 4) ? g_Uhi : g_Ulo;
    const __nv_bfloat16* Ugp =
        Usrc + ((size_t)b * Nn + noff + bnrow) * Cc + (bc & 3) * 8;

    const uint32_t as_base = smem_u32(&As4[0][0][0]);
    const uint32_t bs_base = smem_u32(&Bs4[0][0][0]);

    float acc[2][4][4];
#pragma unroll
    for (int i = 0; i < 2; i++)
#pragma unroll
        for (int j = 0; j < 4; j++)
#pragma unroll
            for (int e = 0; e < 4; e++) acc[i][j][e] = 0.f;

    float4 a0[2], a1[2];
    uint4 u0, u1;
    a0[0] = *(const float4*)(Agp);
    a0[1] = *(const float4*)(Agp + 4);
    a1[0] = *(const float4*)(Agp + (size_t)64 * Cc);
    a1[1] = *(const float4*)(Agp + (size_t)64 * Cc + 4);
    u0 = *(const uint4*)(Ugp);
    u1 = *(const uint4*)(Ugp + (size_t)32 * Cc);

    {
        uint4 h, l;
        split8(a0[0], a0[1], h, l);
        As4[0][arow][akseg ^ am7] = h;
        As4[0][arow][(akseg + 4) ^ am7] = l;
        split8(a1[0], a1[1], h, l);
        As4[0][arow + 64][akseg ^ am7] = h;
        As4[0][arow + 64][(akseg + 4) ^ am7] = l;
        Bs4[0][bnrow][bc ^ bn7] = u0;
        Bs4[0][bnrow + 32][bc ^ bn7] = u1;
    }
    __syncthreads();

    for (int kt = 0; kt < GNT; kt++) {
        const int cur = kt & 1;
        if (kt + 1 < GNT) {
            Agp += 32;
            Ugp += 32;
            a0[0] = *(const float4*)(Agp);
            a0[1] = *(const float4*)(Agp + 4);
            a1[0] = *(const float4*)(Agp + (size_t)64 * Cc);
            a1[1] = *(const float4*)(Agp + (size_t)64 * Cc + 4);
            u0 = *(const uint4*)(Ugp);
            u1 = *(const uint4*)(Ugp + (size_t)32 * Cc);
        }

        const uint32_t asb = as_base + (uint32_t)cur * 16384;
        const uint32_t bsb = bs_base + (uint32_t)cur * 8192;
#pragma unroll
        for (int ks = 0; ks < 2; ks++) {
            const int k0 = ks * 16;
            uint32_t ah[2][4], al[2][4], bhv[2][4], blv[2][4];
#pragma unroll
            for (int mf = 0; mf < 2; mf++) {
                const uint32_t rbase = asb + (uint32_t)(wm + mf * 16 + l15) * 128;
                const int ch = ((k0 >> 3) + lsel) ^ l7;
                const int cl = ((k0 >> 3) + lsel + 4) ^ l7;
                LDSM_X4(ah[mf][0], ah[mf][1], ah[mf][2], ah[mf][3], rbase + ch * 16);
                LDSM_X4(al[mf][0], al[mf][1], al[mf][2], al[mf][3], rbase + cl * 16);
            }
#pragma unroll
            for (int np = 0; np < 2; np++) {
                const int rowN = wn + np * 16 + rowNl;
                const int ch = ((k0 >> 3) + ksel) ^ l7;
                const int cl = ((k0 >> 3) + ksel + 4) ^ l7;
                const uint32_t rb = bsb + (uint32_t)rowN * 128;
                LDSM_X4(bhv[np][0], bhv[np][1], bhv[np][2], bhv[np][3], rb + ch * 16);
                LDSM_X4(blv[np][0], blv[np][1], blv[np][2], blv[np][3], rb + cl * 16);
            }
            EMIT_MMAS_3PASS(acc, ah, al, bhv, blv)
        }

        if (kt + 1 < GNT) {
            const int nxt = cur ^ 1;
            uint4 h, l;
            split8(a0[0], a0[1], h, l);
            As4[nxt][arow][akseg ^ am7] = h;
            As4[nxt][arow][(akseg + 4) ^ am7] = l;
            split8(a1[0], a1[1], h, l);
            As4[nxt][arow + 64][akseg ^ am7] = h;
            As4[nxt][arow + 64][(akseg + 4) ^ am7] = l;
            Bs4[nxt][bnrow][bc ^ bn7] = u0;
            Bs4[nxt][bnrow + 32][bc ^ bn7] = u1;
            __syncthreads();
        }
    }

#pragma unroll
    for (int mf = 0; mf < 2; mf++) {
        const int o = otile + wm + mf * 16 + g;
        const float b0v = bdep[o], b1v = bdep[o + 8];
        const size_t base = (size_t)b * CNsz + (size_t)o * Nn + noff + wn + tc * 2;
#pragma unroll
        for (int nf = 0; nf < 4; nf++) {
            const size_t i0 = base + nf * 8;
            float2 x0 = *(const float2*)(x_ori + i0);
            float2 x1 = *(const float2*)(x_ori + i0 + 8 * Nn);
            *(float2*)(out + i0) =
                make_float2(acc[mf][nf][0] + b0v + x0.x, acc[mf][nf][1] + b0v + x0.y);
            *(float2*)(out + i0 + 8 * Nn) =
                make_float2(acc[mf][nf][2] + b1v + x1.x, acc[mf][nf][3] + b1v + x1.y);
        }
    }
}

// ============================================================================
// Launch
// ============================================================================
extern "C" void kernel_launch(void* const* d_in, const int* in_sizes, int n_in,
                              void* d_out, int out_size)
{
    (void)in_sizes; (void)n_in; (void)out_size;
    const float* x_ori  = (const float*)d_in[0];
    const float* cross  = (const float*)d_in[1];
    const float* W_proj = (const float*)d_in[2];
    const float* b_proj = (const float*)d_in[3];
    const float* W_dep  = (const float*)d_in[4];
    const float* b_dep  = (const float*)d_in[5];
    float* out = (float*)d_out;

    k_proj_mma<<<dim3(32, 6), 256>>>(W_proj, cross, b_proj);
    k_mpart<<<dim3(Hh, Bb), 256>>>(cross);
    k_mred_t<<<128, 256>>>();
    k_out_mma<<<dim3(Bb * Hh, 2), 256>>>(x_ori);
    k_deproj_mma<<<dim3(32, 6), 256>>>(W_dep, b_dep, x_ori, out);
}